// round 2
// baseline (speedup 1.0000x reference)
#include <cuda_runtime.h>

#define N_NODES 100000
#define N_EDGES 1600000
#define ND 128
#define ED 48
#define GD 64
#define NG 64
#define HID 256

// Scratch (device globals — no allocation allowed)
__device__ __align__(16) float g_agg[N_NODES * ED];   // segment-summed edge messages
__device__ __align__(16) float g_gu[NG * HID];        // graph_globals @ W1c + b1

// ---------------- f32x2 packed-math helpers (sm_100+) ----------------
__device__ __forceinline__ unsigned long long pk2(float lo, float hi) {
    unsigned long long r;
    asm("mov.b64 %0, {%1,%2};" : "=l"(r) : "f"(lo), "f"(hi));
    return r;
}
__device__ __forceinline__ void upk2(unsigned long long v, float &lo, float &hi) {
    asm("mov.b64 {%0,%1}, %2;" : "=f"(lo), "=f"(hi) : "l"(v));
}
__device__ __forceinline__ void fma2(unsigned long long &d, unsigned long long a,
                                     unsigned long long b) {
    asm("fma.rn.f32x2 %0, %1, %2, %0;" : "+l"(d) : "l"(a), "l"(b));
}

// ---------------- Kernel 0: zero the aggregation buffer ----------------
__global__ void k_zero() {
    int i = blockIdx.x * blockDim.x + threadIdx.x;
    if (i < (N_NODES * ED) / 4)
        reinterpret_cast<float4*>(g_agg)[i] = make_float4(0.f, 0.f, 0.f, 0.f);
}

// ---------------- Kernel 1: scatter-add edge messages ----------------
// thread = one float4 chunk of one edge (12 chunks/edge). Coalesced reads,
// float atomics into g_agg.
__global__ void k_scatter(const float* __restrict__ edges,
                          const int* __restrict__ recv) {
    int idx = blockIdx.x * blockDim.x + threadIdx.x;
    if (idx >= N_EDGES * 12) return;
    int e = idx / 12;
    int c = idx - e * 12;
    float4 v = reinterpret_cast<const float4*>(edges)[idx];
    int r = recv[e];
    r = min(max(r, 0), N_NODES - 1);   // safety clamp (diagnosable wrong answer > trap)
    float* dst = g_agg + r * ED + c * 4;
    atomicAdd(dst + 0, v.x);
    atomicAdd(dst + 1, v.y);
    atomicAdd(dst + 2, v.z);
    atomicAdd(dst + 3, v.w);
}

// ---------------- Kernel 2: gu[g][j] = b1[j] + globals[g] . W1c[:,j] ----------------
__global__ void k_gu(const float* __restrict__ gg, const float* __restrict__ W1,
                     const float* __restrict__ b1) {
    __shared__ float sg[GD];
    int g = blockIdx.x, j = threadIdx.x;
    if (j < GD) sg[j] = gg[g * GD + j];
    __syncthreads();
    float acc = b1[j];
#pragma unroll
    for (int k = 0; k < GD; k++)
        acc = fmaf(sg[k], W1[(ND + ED + k) * HID + j], acc);
    g_gu[g * HID + j] = acc;
}

// ---------------- Kernel 3: fused MLP ----------------
// Per block: 64 node rows.
// Phase 1: H[64x256] = relu([nodes|agg] @ W1[0:176] + gu[batch])  (K=176)
// Phase 2: out[64x128] = H @ W2 + b2                               (K=256)
// f32x2 packed FMA throughout; H kept in SMEM between phases.
#define SH_R2 (64 * 256)
static const int SMEM_FLOATS = 64 * 256 + 16 * 64 + 16 * 256;  // 21504 floats = 84KB

__global__ void __launch_bounds__(256, 2) k_mlp(
    const float* __restrict__ nodes, const int* __restrict__ batch,
    const float* __restrict__ W1, const float* __restrict__ W2,
    const float* __restrict__ b2, float* __restrict__ out) {
    extern __shared__ float sm[];
    float* sH  = sm;                 // 64 x 256
    float* sA  = sm + SH_R2;         // 16 x 64 (k-major, transposed)
    float* sB  = sA + 16 * 64;       // 16 x 256
    float* sW2 = sm + SH_R2;         // 32 x 128 (reuses sA/sB region in phase 2)

    const int t = threadIdx.x;
    const int tm = t >> 5;   // 0..7  row group (warp-uniform)
    const int tn = t & 31;   // 0..31 col group
    const int m0 = blockIdx.x * 64;

    unsigned long long acc[8][4];
#pragma unroll
    for (int i = 0; i < 8; i++)
#pragma unroll
        for (int j = 0; j < 4; j++) acc[i][j] = 0ull;

    const int lrow = t >> 2;  // A-tile load: row
    const int lkq  = t & 3;   // A-tile load: k quad

    // ---- Phase 1: K = 128 (nodes) + 48 (agg) = 11 chunks of 16 ----
    for (int kb = 0; kb < 11; ++kb) {
        {
            const float* src;
            int stride, kofs;
            if (kb < 8) { src = nodes; stride = ND; kofs = kb * 16; }
            else        { src = g_agg; stride = ED; kofs = (kb - 8) * 16; }
            int gr = m0 + lrow;
            float4 v = make_float4(0.f, 0.f, 0.f, 0.f);
            if (gr < N_NODES)
                v = *reinterpret_cast<const float4*>(src + gr * stride + kofs + lkq * 4);
            sA[(lkq * 4 + 0) * 64 + lrow] = v.x;
            sA[(lkq * 4 + 1) * 64 + lrow] = v.y;
            sA[(lkq * 4 + 2) * 64 + lrow] = v.z;
            sA[(lkq * 4 + 3) * 64 + lrow] = v.w;
        }
        {
            int kbase = kb * 16;
#pragma unroll
            for (int i = 0; i < 4; i++) {
                int f = t + i * 256;       // float4 index, 1024 total
                int k = f >> 6;            // 64 float4 per 256-wide row
                int col = (f & 63) << 2;
                *reinterpret_cast<float4*>(sB + k * 256 + col) =
                    *reinterpret_cast<const float4*>(W1 + (kbase + k) * HID + col);
            }
        }
        __syncthreads();
#pragma unroll
        for (int kk = 0; kk < 16; ++kk) {
            float4 a0 = *reinterpret_cast<const float4*>(sA + kk * 64 + tm * 8);
            float4 a1 = *reinterpret_cast<const float4*>(sA + kk * 64 + tm * 8 + 4);
            float4 b0 = *reinterpret_cast<const float4*>(sB + kk * 256 + tn * 8);
            float4 b1 = *reinterpret_cast<const float4*>(sB + kk * 256 + tn * 8 + 4);
            unsigned long long bp[4];
            bp[0] = pk2(b0.x, b0.y);
            bp[1] = pk2(b0.z, b0.w);
            bp[2] = pk2(b1.x, b1.y);
            bp[3] = pk2(b1.z, b1.w);
            float ar[8] = {a0.x, a0.y, a0.z, a0.w, a1.x, a1.y, a1.z, a1.w};
#pragma unroll
            for (int i = 0; i < 8; i++) {
                unsigned long long ap = pk2(ar[i], ar[i]);
                fma2(acc[i][0], ap, bp[0]);
                fma2(acc[i][1], ap, bp[1]);
                fma2(acc[i][2], ap, bp[2]);
                fma2(acc[i][3], ap, bp[3]);
            }
        }
        __syncthreads();
    }

    // ---- Epilogue 1: + gu[batch], ReLU, spill H to SMEM ----
#pragma unroll
    for (int i = 0; i < 8; i++) {
        int gr = m0 + tm * 8 + i;
        int g = (gr < N_NODES) ? batch[gr] : 0;
        g = min(max(g, 0), NG - 1);    // safety clamp
        const float* gu = g_gu + g * HID;
#pragma unroll
        for (int j = 0; j < 4; j++) {
            float lo, hi;
            upk2(acc[i][j], lo, hi);
            int c = tn * 8 + j * 2;
            lo = fmaxf(lo + gu[c], 0.f);
            hi = fmaxf(hi + gu[c + 1], 0.f);
            sH[(tm * 8 + i) * 256 + c]     = lo;
            sH[(tm * 8 + i) * 256 + c + 1] = hi;
        }
    }
    __syncthreads();

    // ---- Phase 2: out = H @ W2 + b2, K = 256 in chunks of 32 ----
    unsigned long long acc2[8][2];
#pragma unroll
    for (int i = 0; i < 8; i++) { acc2[i][0] = 0ull; acc2[i][1] = 0ull; }
    float4 bias = *reinterpret_cast<const float4*>(b2 + tn * 4);

    for (int kb = 0; kb < 8; ++kb) {
#pragma unroll
        for (int i = 0; i < 4; i++) {
            int f = t + i * 256;       // 1024 float4 = 32 x 128 floats
            int k = f >> 5;            // 32 float4 per 128-wide row
            int col = (f & 31) << 2;
            *reinterpret_cast<float4*>(sW2 + k * 128 + col) =
                *reinterpret_cast<const float4*>(W2 + (kb * 32 + k) * ND + col);
        }
        __syncthreads();
#pragma unroll
        for (int kk = 0; kk < 32; ++kk) {
            float4 b = *reinterpret_cast<const float4*>(sW2 + kk * 128 + tn * 4);
            unsigned long long bp0 = pk2(b.x, b.y);
            unsigned long long bp1 = pk2(b.z, b.w);
#pragma unroll
            for (int i = 0; i < 8; i++) {
                float a = sH[(tm * 8 + i) * 256 + kb * 32 + kk];  // warp broadcast
                unsigned long long ap = pk2(a, a);
                fma2(acc2[i][0], ap, bp0);
                fma2(acc2[i][1], ap, bp1);
            }
        }
        __syncthreads();
    }

    // ---- Epilogue 2: + b2, store ----
#pragma unroll
    for (int i = 0; i < 8; i++) {
        int gr = m0 + tm * 8 + i;
        if (gr < N_NODES) {
            float4 o;
            upk2(acc2[i][0], o.x, o.y);
            upk2(acc2[i][1], o.z, o.w);
            o.x += bias.x; o.y += bias.y; o.z += bias.z; o.w += bias.w;
            *reinterpret_cast<float4*>(out + gr * ND + tn * 4) = o;
        }
    }
}

// ---------------- launch ----------------
extern "C" void kernel_launch(void* const* d_in, const int* in_sizes, int n_in,
                              void* d_out, int out_size) {
    const float* nodes   = (const float*)d_in[0];
    const float* edges   = (const float*)d_in[1];
    const int*   eindex  = (const int*)d_in[2];    // int64 in reference -> int32 in harness
    const int*   batch   = (const int*)d_in[3];    // int64 in reference -> int32 in harness
    const float* globals = (const float*)d_in[4];
    const float* W1      = (const float*)d_in[5];
    const float* b1      = (const float*)d_in[6];
    const float* W2      = (const float*)d_in[7];
    const float* b2      = (const float*)d_in[8];
    float*       out     = (float*)d_out;

    k_zero<<<(N_NODES * ED / 4 + 1023) / 1024, 1024>>>();
    k_scatter<<<(N_EDGES * 12) / 256, 256>>>(edges, eindex + N_EDGES);  // recv row
    k_gu<<<NG, HID>>>(globals, W1, b1);

    const int smem_bytes = SMEM_FLOATS * (int)sizeof(float);
    cudaFuncSetAttribute(k_mlp, cudaFuncAttributeMaxDynamicSharedMemorySize, smem_bytes);
    k_mlp<<<(N_NODES + 63) / 64, 256, smem_bytes>>>(nodes, batch, W1, W2, b2, out);
}

// round 3
// speedup vs baseline: 1.4353x; 1.4353x over previous
#include <cuda_runtime.h>

#define N_NODES 100000
#define N_EDGES 1600000
#define ND 128
#define ED 48
#define GD 64
#define NG 64
#define HID 256

// Scratch (device globals — no allocation allowed)
__device__ __align__(16) float g_agg[N_NODES * ED];
__device__ __align__(16) float g_gu[NG * HID];

// ---------------- helpers ----------------
__device__ __forceinline__ unsigned long long pk2(float lo, float hi) {
    unsigned long long r;
    asm("mov.b64 %0, {%1,%2};" : "=l"(r) : "f"(lo), "f"(hi));
    return r;
}
__device__ __forceinline__ void upk2(unsigned long long v, float &lo, float &hi) {
    asm("mov.b64 {%0,%1}, %2;" : "=f"(lo), "=f"(hi) : "l"(v));
}
__device__ __forceinline__ void fma2(unsigned long long &d, unsigned long long a,
                                     unsigned long long b) {
    asm("fma.rn.f32x2 %0, %1, %2, %0;" : "+l"(d) : "l"(a), "l"(b));
}
__device__ __forceinline__ void cp16(float* smem_dst, const float* gmem_src) {
    unsigned s = (unsigned)__cvta_generic_to_shared(smem_dst);
    asm volatile("cp.async.cg.shared.global [%0], [%1], 16;" :: "r"(s), "l"(gmem_src));
}
#define CP_COMMIT asm volatile("cp.async.commit_group;")
#define CP_WAIT0  asm volatile("cp.async.wait_group 0;")

// ---------------- Kernel 0: zero agg ----------------
__global__ void k_zero() {
    int i = blockIdx.x * blockDim.x + threadIdx.x;
    if (i < (N_NODES * ED) / 4)
        reinterpret_cast<float4*>(g_agg)[i] = make_float4(0.f, 0.f, 0.f, 0.f);
}

// ---------------- Kernel 1: scatter-add (vector red) ----------------
__global__ void k_scatter(const float* __restrict__ edges,
                          const int* __restrict__ recv) {
    int idx = blockIdx.x * blockDim.x + threadIdx.x;
    if (idx >= N_EDGES * 12) return;
    int e = idx / 12;
    int c = idx - e * 12;
    float4 v = reinterpret_cast<const float4*>(edges)[idx];
    int r = recv[e];
    r = min(max(r, 0), N_NODES - 1);
    float* dst = g_agg + r * ED + c * 4;
    asm volatile("red.global.add.v4.f32 [%0], {%1,%2,%3,%4};"
                 :: "l"(dst), "f"(v.x), "f"(v.y), "f"(v.z), "f"(v.w) : "memory");
}

// ---------------- Kernel 2: gu = globals @ W1c + b1 ----------------
__global__ void k_gu(const float* __restrict__ gg, const float* __restrict__ W1,
                     const float* __restrict__ b1) {
    __shared__ float sg[GD];
    int g = blockIdx.x, j = threadIdx.x;
    if (j < GD) sg[j] = gg[g * GD + j];
    __syncthreads();
    float acc = b1[j];
#pragma unroll
    for (int k = 0; k < GD; k++)
        acc = fmaf(sg[k], W1[(ND + ED + k) * HID + j], acc);
    g_gu[g * HID + j] = acc;
}

// ---------------- Kernel 3: fused MLP ----------------
// 64 rows/block, 256 threads.
// SMEM layout (floats):
//   sH : [0, 16384)                 64 x 256
//   sB : [16384, 24576)             2 x (16 x 256)  — W1 chunks / W2 chunks (2 x 32 x 128)
//   sA : [24576, 26752)             2 x (16 x 68)   — A k-major, padded stride 68
#define SH_OFF  0
#define SB_OFF  16384
#define SA_OFF  24576
#define SA_STRIDE 68
#define SMEM_FLOATS 26752   // 107,008 bytes

__global__ void __launch_bounds__(256, 2) k_mlp(
    const float* __restrict__ nodes, const int* __restrict__ batch,
    const float* __restrict__ W1, const float* __restrict__ W2,
    const float* __restrict__ b2, float* __restrict__ out) {
    extern __shared__ float sm[];
    float* sH = sm + SH_OFF;
    float* sB = sm + SB_OFF;
    float* sA = sm + SA_OFF;

    const int t = threadIdx.x;
    const int m0 = blockIdx.x * 64;

    // phase-1 thread mapping: 8 warps = 8 row-groups (8 rows), 32 lanes = col split
    const int tm = t >> 5;   // rows tm*8 .. tm*8+7
    const int tn = t & 31;   // cols tn*4 and 128+tn*4
    // loaders
    const int lrow = t >> 2, lkq = t & 3;

    // ---------------- Phase 1 ----------------
    unsigned long long acc[8][4];
#pragma unroll
    for (int i = 0; i < 8; i++)
#pragma unroll
        for (int j = 0; j < 4; j++) acc[i][j] = 0ull;

    // A chunk load (global -> regs), guarded
    auto ldA = [&](int kb) -> float4 {
        const float* src; int stride, kofs;
        if (kb < 8) { src = nodes; stride = ND; kofs = kb * 16; }
        else        { src = g_agg; stride = ED; kofs = (kb - 8) * 16; }
        int gr = m0 + lrow;
        float4 v = make_float4(0.f, 0.f, 0.f, 0.f);
        if (gr < N_NODES)
            v = *reinterpret_cast<const float4*>(src + gr * stride + kofs + lkq * 4);
        return v;
    };
    auto stA = [&](int kb, float4 v) {
        float* dst = sA + (kb & 1) * (16 * SA_STRIDE);
        dst[(lkq * 4 + 0) * SA_STRIDE + lrow] = v.x;
        dst[(lkq * 4 + 1) * SA_STRIDE + lrow] = v.y;
        dst[(lkq * 4 + 2) * SA_STRIDE + lrow] = v.z;
        dst[(lkq * 4 + 3) * SA_STRIDE + lrow] = v.w;
    };
    auto cpB = [&](int kb) {
        float* dst = sB + (kb & 1) * 4096;
        const float* src = W1 + kb * 16 * HID;
#pragma unroll
        for (int i = 0; i < 4; i++) {
            int f = t + i * 256;            // 0..1023 float4 tiles
            int k = f >> 6, col = (f & 63) << 2;
            cp16(dst + k * 256 + col, src + k * 256 + col);
        }
    };

    float4 va = ldA(0);
    cpB(0); CP_COMMIT;
    stA(0, va);
    va = ldA(1);

    for (int kb = 0; kb < 11; ++kb) {
        CP_WAIT0;
        __syncthreads();
        if (kb < 10) {
            stA(kb + 1, va);
            cpB(kb + 1); CP_COMMIT;
            if (kb < 9) va = ldA(kb + 2);
        }
        const float* A = sA + (kb & 1) * (16 * SA_STRIDE);
        const float* B = sB + (kb & 1) * 4096;
#pragma unroll
        for (int kk = 0; kk < 16; ++kk) {
            float4 a0 = *reinterpret_cast<const float4*>(A + kk * SA_STRIDE + tm * 8);
            float4 a1 = *reinterpret_cast<const float4*>(A + kk * SA_STRIDE + tm * 8 + 4);
            ulonglong2 b0 = *reinterpret_cast<const ulonglong2*>(B + kk * 256 + tn * 4);
            ulonglong2 b1 = *reinterpret_cast<const ulonglong2*>(B + kk * 256 + 128 + tn * 4);
            float ar[8] = {a0.x, a0.y, a0.z, a0.w, a1.x, a1.y, a1.z, a1.w};
#pragma unroll
            for (int i = 0; i < 8; i++) {
                unsigned long long ap = pk2(ar[i], ar[i]);
                fma2(acc[i][0], ap, b0.x);
                fma2(acc[i][1], ap, b0.y);
                fma2(acc[i][2], ap, b1.x);
                fma2(acc[i][3], ap, b1.y);
            }
        }
    }

    // ---- Epilogue 1: + gu[batch], ReLU, spill to sH ----
    {
        int c0 = tn * 4, c1 = 128 + tn * 4;
#pragma unroll
        for (int i = 0; i < 8; i++) {
            int row = tm * 8 + i;
            int gr = m0 + row;
            int g = (gr < N_NODES) ? batch[gr] : 0;
            g = min(max(g, 0), NG - 1);
            const float* gu = g_gu + g * HID;
            float4 g0 = *reinterpret_cast<const float4*>(gu + c0);
            float4 g1 = *reinterpret_cast<const float4*>(gu + c1);
            float4 o0, o1;
            upk2(acc[i][0], o0.x, o0.y);
            upk2(acc[i][1], o0.z, o0.w);
            upk2(acc[i][2], o1.x, o1.y);
            upk2(acc[i][3], o1.z, o1.w);
            o0.x = fmaxf(o0.x + g0.x, 0.f); o0.y = fmaxf(o0.y + g0.y, 0.f);
            o0.z = fmaxf(o0.z + g0.z, 0.f); o0.w = fmaxf(o0.w + g0.w, 0.f);
            o1.x = fmaxf(o1.x + g1.x, 0.f); o1.y = fmaxf(o1.y + g1.y, 0.f);
            o1.z = fmaxf(o1.z + g1.z, 0.f); o1.w = fmaxf(o1.w + g1.w, 0.f);
            *reinterpret_cast<float4*>(sH + row * 256 + c0) = o0;
            *reinterpret_cast<float4*>(sH + row * 256 + c1) = o1;
        }
    }
    __syncthreads();   // sH complete; sB free

    // ---------------- Phase 2 ----------------
    // 16x16 mapping: tm2 = 4 rows each, tn2 = cols {tn2*4, 64+tn2*4}
    const int tm2 = t >> 4;   // 0..15
    const int tn2 = t & 15;   // 0..15

    auto cpW = [&](int kb) {
        float* dst = sB + (kb & 1) * 4096;
        const float* src = W2 + kb * 32 * ND;
#pragma unroll
        for (int i = 0; i < 4; i++) {
            int f = t + i * 256;            // 0..1023 float4 tiles (32 x 128 floats)
            int k = f >> 5, col = (f & 31) << 2;
            cp16(dst + k * 128 + col, src + k * 128 + col);
        }
    };

    unsigned long long acc2[4][4];
#pragma unroll
    for (int i = 0; i < 4; i++)
#pragma unroll
        for (int j = 0; j < 4; j++) acc2[i][j] = 0ull;

    cpW(0); CP_COMMIT;
    for (int kb = 0; kb < 8; ++kb) {
        CP_WAIT0;
        __syncthreads();
        if (kb < 7) { cpW(kb + 1); CP_COMMIT; }
        const float* W = sB + (kb & 1) * 4096;
#pragma unroll
        for (int kt = 0; kt < 8; ++kt) {     // groups of 4 k
            float hv[4][4];
#pragma unroll
            for (int i = 0; i < 4; i++) {
                float4 h = *reinterpret_cast<const float4*>(
                    sH + (tm2 * 4 + i) * 256 + kb * 32 + kt * 4);
                hv[i][0] = h.x; hv[i][1] = h.y; hv[i][2] = h.z; hv[i][3] = h.w;
            }
#pragma unroll
            for (int j = 0; j < 4; j++) {
                int kk = kt * 4 + j;
                ulonglong2 w0 = *reinterpret_cast<const ulonglong2*>(W + kk * 128 + tn2 * 4);
                ulonglong2 w1 = *reinterpret_cast<const ulonglong2*>(W + kk * 128 + 64 + tn2 * 4);
#pragma unroll
                for (int i = 0; i < 4; i++) {
                    unsigned long long ap = pk2(hv[i][j], hv[i][j]);
                    fma2(acc2[i][0], ap, w0.x);
                    fma2(acc2[i][1], ap, w0.y);
                    fma2(acc2[i][2], ap, w1.x);
                    fma2(acc2[i][3], ap, w1.y);
                }
            }
        }
    }

    // ---- Epilogue 2 ----
    {
        int c0 = tn2 * 4, c1 = 64 + tn2 * 4;
        float4 bias0 = *reinterpret_cast<const float4*>(b2 + c0);
        float4 bias1 = *reinterpret_cast<const float4*>(b2 + c1);
#pragma unroll
        for (int i = 0; i < 4; i++) {
            int gr = m0 + tm2 * 4 + i;
            if (gr < N_NODES) {
                float4 o0, o1;
                upk2(acc2[i][0], o0.x, o0.y);
                upk2(acc2[i][1], o0.z, o0.w);
                upk2(acc2[i][2], o1.x, o1.y);
                upk2(acc2[i][3], o1.z, o1.w);
                o0.x += bias0.x; o0.y += bias0.y; o0.z += bias0.z; o0.w += bias0.w;
                o1.x += bias1.x; o1.y += bias1.y; o1.z += bias1.z; o1.w += bias1.w;
                *reinterpret_cast<float4*>(out + gr * ND + c0) = o0;
                *reinterpret_cast<float4*>(out + gr * ND + c1) = o1;
            }
        }
    }
}

// ---------------- launch ----------------
extern "C" void kernel_launch(void* const* d_in, const int* in_sizes, int n_in,
                              void* d_out, int out_size) {
    const float* nodes   = (const float*)d_in[0];
    const float* edges   = (const float*)d_in[1];
    const int*   eindex  = (const int*)d_in[2];
    const int*   batch   = (const int*)d_in[3];
    const float* globals = (const float*)d_in[4];
    const float* W1      = (const float*)d_in[5];
    const float* b1      = (const float*)d_in[6];
    const float* W2      = (const float*)d_in[7];
    const float* b2      = (const float*)d_in[8];
    float*       out     = (float*)d_out;

    k_zero<<<(N_NODES * ED / 4 + 1023) / 1024, 1024>>>();
    k_scatter<<<(N_EDGES * 12) / 256, 256>>>(edges, eindex + N_EDGES);
    k_gu<<<NG, HID>>>(globals, W1, b1);

    const int smem_bytes = SMEM_FLOATS * (int)sizeof(float);
    cudaFuncSetAttribute(k_mlp, cudaFuncAttributeMaxDynamicSharedMemorySize, smem_bytes);
    k_mlp<<<(N_NODES + 63) / 64, 256, smem_bytes>>>(nodes, batch, W1, W2, b2, out);
}

// round 6
// speedup vs baseline: 1.8962x; 1.3211x over previous
#include <cuda_runtime.h>
#include <cuda_bf16.h>
#include <cstdint>

#define N_NODES 100000
#define N_EDGES 1600000
#define ND 128
#define ED 48
#define GD 64
#define NG 64
#define HID 256

// ---------------- device scratch ----------------
__device__ __align__(16) float g_agg[N_NODES * ED];
__device__ __align__(16) float g_gu[NG * HID];
// W1^T chunked blobs: [12 chunks][256 n][24 k] bf16 (k 16 data + 8 pad)
__device__ __align__(16) __nv_bfloat16 g_w1t_h[12 * 256 * 24];
__device__ __align__(16) __nv_bfloat16 g_w1t_l[12 * 256 * 24];
// W2^T chunked blobs: [16 chunks][128 n][24 k]
__device__ __align__(16) __nv_bfloat16 g_w2t_h[16 * 128 * 24];
__device__ __align__(16) __nv_bfloat16 g_w2t_l[16 * 128 * 24];

// ---------------- helpers ----------------
__device__ __forceinline__ uint32_t smem_u32(const void* p) {
    return (uint32_t)__cvta_generic_to_shared(p);
}
__device__ __forceinline__ void cp16(char* dst, const char* src) {
    uint32_t s = smem_u32(dst);
    asm volatile("cp.async.cg.shared.global [%0], [%1], 16;" :: "r"(s), "l"(src));
}
#define CP_COMMIT asm volatile("cp.async.commit_group;")
__device__ __forceinline__ void cp_wait0() { asm volatile("cp.async.wait_group 0;"); }
__device__ __forceinline__ void cp_wait1() { asm volatile("cp.async.wait_group 1;"); }

__device__ __forceinline__ void ldsm4(uint32_t addr, uint32_t r[4]) {
    asm volatile("ldmatrix.sync.aligned.m8n8.x4.shared.b16 {%0,%1,%2,%3}, [%4];"
                 : "=r"(r[0]), "=r"(r[1]), "=r"(r[2]), "=r"(r[3]) : "r"(addr));
}
__device__ __forceinline__ void mma16816(float d[4], const uint32_t a[4],
                                         uint32_t b0, uint32_t b1) {
    asm volatile("mma.sync.aligned.m16n8k16.row.col.f32.bf16.bf16.f32 "
                 "{%0,%1,%2,%3}, {%4,%5,%6,%7}, {%8,%9}, {%0,%1,%2,%3};"
                 : "+f"(d[0]), "+f"(d[1]), "+f"(d[2]), "+f"(d[3])
                 : "r"(a[0]), "r"(a[1]), "r"(a[2]), "r"(a[3]), "r"(b0), "r"(b1));
}
// hi/lo bf16 split pair store (element offset, 2 consecutive elems)
__device__ __forceinline__ void st_pair(char* hiB, char* loB, int elemOff,
                                        float a, float b) {
    __nv_bfloat16 h0 = __float2bfloat16(a), h1 = __float2bfloat16(b);
    __nv_bfloat162 hp; hp.x = h0; hp.y = h1;
    __nv_bfloat162 lp;
    lp.x = __float2bfloat16(a - __bfloat162float(h0));
    lp.y = __float2bfloat16(b - __bfloat162float(h1));
    *(__nv_bfloat162*)(hiB + elemOff * 2) = hp;
    *(__nv_bfloat162*)(loB + elemOff * 2) = lp;
}

// ---------------- Kernel: zero agg ----------------
__global__ void k_zero() {
    int i = blockIdx.x * blockDim.x + threadIdx.x;
    if (i < (N_NODES * ED) / 4)
        reinterpret_cast<float4*>(g_agg)[i] = make_float4(0.f, 0.f, 0.f, 0.f);
}

// ---------------- Kernel: scatter-add (vector red) ----------------
__global__ void k_scatter(const float* __restrict__ edges,
                          const int* __restrict__ recv) {
    int idx = blockIdx.x * blockDim.x + threadIdx.x;
    if (idx >= N_EDGES * 12) return;
    int e = idx / 12;
    int c = idx - e * 12;
    float4 v = reinterpret_cast<const float4*>(edges)[idx];
    int r = recv[e];
    r = min(max(r, 0), N_NODES - 1);
    float* dst = g_agg + r * ED + c * 4;
    asm volatile("red.global.add.v4.f32 [%0], {%1,%2,%3,%4};"
                 :: "l"(dst), "f"(v.x), "f"(v.y), "f"(v.z), "f"(v.w) : "memory");
}

// ---------------- Kernel: gu = globals @ W1c + b1 (fp32) ----------------
__global__ void k_gu(const float* __restrict__ gg, const float* __restrict__ W1,
                     const float* __restrict__ b1) {
    __shared__ float sg[GD];
    int g = blockIdx.x, j = threadIdx.x;
    if (j < GD) sg[j] = gg[g * GD + j];
    __syncthreads();
    float acc = b1[j];
#pragma unroll
    for (int k = 0; k < GD; k++)
        acc = fmaf(sg[k], W1[(ND + ED + k) * HID + j], acc);
    g_gu[g * HID + j] = acc;
}

// ---------------- prep: W1^T hi/lo chunked [12][256][24] ----------------
__global__ void k_w1t(const float* __restrict__ W1) {
    int idx = blockIdx.x * 256 + threadIdx.x;   // 49152 = 192 k x 256 n
    int n = idx & 255, kg = idx >> 8;
    float v = (kg < ND + ED) ? W1[kg * HID + n] : 0.f;
    __nv_bfloat16 h = __float2bfloat16(v);
    __nv_bfloat16 l = __float2bfloat16(v - __bfloat162float(h));
    int chunk = kg >> 4, kc = kg & 15;
    int off = chunk * (256 * 24) + n * 24 + kc;
    g_w1t_h[off] = h;
    g_w1t_l[off] = l;
}

// ---------------- prep: W2^T hi/lo chunked [16][128][24] ----------------
__global__ void k_w2t(const float* __restrict__ W2) {
    int idx = blockIdx.x * 256 + threadIdx.x;   // 32768 = 256 k x 128 n
    int n = idx & 127, kg = idx >> 7;
    float v = W2[kg * ND + n];
    __nv_bfloat16 h = __float2bfloat16(v);
    __nv_bfloat16 l = __float2bfloat16(v - __bfloat162float(h));
    int chunk = kg >> 4, kc = kg & 15;
    int off = chunk * (128 * 24) + n * 24 + kc;
    g_w2t_h[off] = h;
    g_w2t_l[off] = l;
}

// ---------------- fused MLP via mma.sync bf16 hi/lo ----------------
// SMEM (bytes):
//  phase1: A_hi [0,51200) 128x200 elems, A_lo [51200,102400)
//  phase2: H_hi [0,67584) 128x264 elems, H_lo [67584,135168)   (reuses A region)
//  B buffers at 135168: phase1 2 bufs x 24576 (hi 12288 + lo 12288)
//                       phase2 2 bufs x 12288 (hi 6144  + lo 6144)
#define AH_OFF 0
#define AL_OFF 51200
#define HH_OFF 0
#define HL_OFF 67584
#define BB_OFF 135168
#define SMEM_BYTES 184320
#define SA_B 400   // A row stride bytes
#define SH_B 528   // H row stride bytes

__global__ void __launch_bounds__(256, 1) k_mlp_mma(
    const float* __restrict__ nodes, const int* __restrict__ batch,
    const float* __restrict__ b2, float* __restrict__ out) {
    extern __shared__ char smem[];
    const uint32_t sbase = smem_u32(smem);
    const int t = threadIdx.x;
    const int wid = t >> 5, lane = t & 31;
    const int m0 = blockIdx.x * 128;
    const int mw = wid >> 2;          // 0..1
    const int nw = wid & 3;           // 0..3
    const int rA = mw * 64;
    const int lq = lane >> 2;         // 0..7
    const int lr = lane & 3;          // 0..3

    // ---- prefetch B1 chunk 0 ----
    auto copyB1 = [&](int kc) {
        char* dst = smem + BB_OFF + (kc & 1) * 24576;
        const char* sh = (const char*)g_w1t_h + kc * 12288;
        const char* sl = (const char*)g_w1t_l + kc * 12288;
#pragma unroll
        for (int i = 0; i < 3; i++) {
            int u = (t + i * 256) * 16;
            cp16(dst + u, sh + u);
            cp16(dst + 12288 + u, sl + u);
        }
    };
    auto copyB2 = [&](int kc) {
        char* dst = smem + BB_OFF + (kc & 1) * 12288;
        const char* sh = (const char*)g_w2t_h + kc * 6144;
        const char* sl = (const char*)g_w2t_l + kc * 6144;
#pragma unroll
        for (int i = 0; i < 2; i++) {
            int u = t + i * 256;
            if (u < 384) {
                cp16(dst + u * 16, sh + u * 16);
                cp16(dst + 6144 + u * 16, sl + u * 16);
            }
        }
    };

    copyB1(0); CP_COMMIT;

    // ---- stage X = [nodes | agg | pad] -> A hi/lo smem ----
    {
        char* aH = smem + AH_OFF;
        char* aL = smem + AL_OFF;
#pragma unroll
        for (int i = 0; i < 16; i++) {            // nodes: 128 rows x 32 f4
            int f4 = t + i * 256;
            int row = f4 >> 5, q = f4 & 31;
            int gr = m0 + row;
            float4 v = make_float4(0.f, 0.f, 0.f, 0.f);
            if (gr < N_NODES) v = reinterpret_cast<const float4*>(nodes + (size_t)gr * ND)[q];
            int off = row * 200 + q * 4;
            st_pair(aH, aL, off,     v.x, v.y);
            st_pair(aH, aL, off + 2, v.z, v.w);
        }
#pragma unroll
        for (int i = 0; i < 6; i++) {             // agg: 128 rows x 12 f4
            int f4 = t + i * 256;
            int row = f4 / 12, q = f4 - row * 12;
            int gr = m0 + row;
            float4 v = make_float4(0.f, 0.f, 0.f, 0.f);
            if (gr < N_NODES) v = reinterpret_cast<const float4*>(g_agg + (size_t)gr * ED)[q];
            int off = row * 200 + 128 + q * 4;
            st_pair(aH, aL, off,     v.x, v.y);
            st_pair(aH, aL, off + 2, v.z, v.w);
        }
#pragma unroll
        for (int i = 0; i < 4; i++) {             // pad k 176..191
            int idx = t + i * 256;                // 1024 = 128 rows x 8 pairs
            int row = idx >> 3, s = idx & 7;
            st_pair(aH, aL, row * 200 + 176 + s * 2, 0.f, 0.f);
        }
    }

    // per-lane ldmatrix address bases
    const uint32_t aRowH = sbase + AH_OFF + (rA + (lane & 15)) * SA_B + (lane >> 4) * 16;
    const uint32_t aRowL = aRowH + (AL_OFF - AH_OFF);
    const uint32_t bRow1 = (nw * 64 + (lane & 15)) * 48 + (lane >> 4) * 16;
    const uint32_t bRow2 = (nw * 32 + (lane & 15)) * 48 + (lane >> 4) * 16;

    // ---------------- Phase 1 ----------------
    float acc[4][8][4];
#pragma unroll
    for (int a = 0; a < 4; a++)
#pragma unroll
        for (int b = 0; b < 8; b++)
#pragma unroll
            for (int c = 0; c < 4; c++) acc[a][b][c] = 0.f;

    for (int kc = 0; kc < 12; ++kc) {
        if (kc < 11) { copyB1(kc + 1); CP_COMMIT; cp_wait1(); }
        else cp_wait0();
        __syncthreads();

        uint32_t bufH = sbase + BB_OFF + (kc & 1) * 24576;
        uint32_t bufL = bufH + 12288;
        uint32_t ah[4][4], al[4][4], bh[4][4], bl[4][4];
#pragma unroll
        for (int mi = 0; mi < 4; mi++) {
            ldsm4(aRowH + mi * (16 * SA_B) + kc * 32, ah[mi]);
            ldsm4(aRowL + mi * (16 * SA_B) + kc * 32, al[mi]);
        }
#pragma unroll
        for (int j = 0; j < 4; j++) {
            ldsm4(bufH + bRow1 + j * 768, bh[j]);
            ldsm4(bufL + bRow1 + j * 768, bl[j]);
        }
#pragma unroll
        for (int mi = 0; mi < 4; mi++)
#pragma unroll
            for (int j = 0; j < 4; j++) {
                mma16816(acc[mi][2 * j],     ah[mi], bh[j][0], bh[j][2]);
                mma16816(acc[mi][2 * j],     ah[mi], bl[j][0], bl[j][2]);
                mma16816(acc[mi][2 * j],     al[mi], bh[j][0], bh[j][2]);
                mma16816(acc[mi][2 * j + 1], ah[mi], bh[j][1], bh[j][3]);
                mma16816(acc[mi][2 * j + 1], ah[mi], bl[j][1], bl[j][3]);
                mma16816(acc[mi][2 * j + 1], al[mi], bh[j][1], bh[j][3]);
            }
        __syncthreads();
    }

    // prefetch B2 chunk 0 (B1 buffers fully drained)
    copyB2(0); CP_COMMIT;

    // ---- Epilogue 1: +gu[batch], ReLU, hi/lo -> H smem ----
    {
        char* hH = smem + HH_OFF;
        char* hL = smem + HL_OFF;
        int colB = nw * 64 + lr * 2;
#pragma unroll
        for (int mi = 0; mi < 4; mi++) {
            int r0 = rA + mi * 16 + lq;
            int r1 = r0 + 8;
            int g0 = batch[min(m0 + r0, N_NODES - 1)];
            int g1 = batch[min(m0 + r1, N_NODES - 1)];
            g0 = min(max(g0, 0), NG - 1);
            g1 = min(max(g1, 0), NG - 1);
            const float* gu0 = g_gu + g0 * HID;
            const float* gu1 = g_gu + g1 * HID;
#pragma unroll
            for (int nf = 0; nf < 8; nf++) {
                int col = colB + nf * 8;
                float2 u0 = *(const float2*)(gu0 + col);
                float2 u1 = *(const float2*)(gu1 + col);
                float v00 = fmaxf(acc[mi][nf][0] + u0.x, 0.f);
                float v01 = fmaxf(acc[mi][nf][1] + u0.y, 0.f);
                float v10 = fmaxf(acc[mi][nf][2] + u1.x, 0.f);
                float v11 = fmaxf(acc[mi][nf][3] + u1.y, 0.f);
                st_pair(hH, hL, r0 * 264 + col, v00, v01);
                st_pair(hH, hL, r1 * 264 + col, v10, v11);
            }
        }
    }
    __syncthreads();

    // ---------------- Phase 2 ----------------
    const uint32_t hRowH = sbase + HH_OFF + (rA + (lane & 15)) * SH_B + (lane >> 4) * 16;
    const uint32_t hRowL = hRowH + (HL_OFF - HH_OFF);

    float acc2[4][4][4];
#pragma unroll
    for (int a = 0; a < 4; a++)
#pragma unroll
        for (int b = 0; b < 4; b++)
#pragma unroll
            for (int c = 0; c < 4; c++) acc2[a][b][c] = 0.f;

    for (int kc = 0; kc < 16; ++kc) {
        if (kc < 15) { copyB2(kc + 1); CP_COMMIT; cp_wait1(); }
        else cp_wait0();
        __syncthreads();

        uint32_t bufH = sbase + BB_OFF + (kc & 1) * 12288;
        uint32_t bufL = bufH + 6144;
        uint32_t ah[4][4], al[4][4], bh[2][4], bl[2][4];
#pragma unroll
        for (int mi = 0; mi < 4; mi++) {
            ldsm4(hRowH + mi * (16 * SH_B) + kc * 32, ah[mi]);
            ldsm4(hRowL + mi * (16 * SH_B) + kc * 32, al[mi]);
        }
#pragma unroll
        for (int j = 0; j < 2; j++) {
            ldsm4(bufH + bRow2 + j * 768, bh[j]);
            ldsm4(bufL + bRow2 + j * 768, bl[j]);
        }
#pragma unroll
        for (int mi = 0; mi < 4; mi++)
#pragma unroll
            for (int j = 0; j < 2; j++) {
                mma16816(acc2[mi][2 * j],     ah[mi], bh[j][0], bh[j][2]);
                mma16816(acc2[mi][2 * j],     ah[mi], bl[j][0], bl[j][2]);
                mma16816(acc2[mi][2 * j],     al[mi], bh[j][0], bh[j][2]);
                mma16816(acc2[mi][2 * j + 1], ah[mi], bh[j][1], bh[j][3]);
                mma16816(acc2[mi][2 * j + 1], ah[mi], bl[j][1], bl[j][3]);
                mma16816(acc2[mi][2 * j + 1], al[mi], bh[j][1], bh[j][3]);
            }
        __syncthreads();
    }

    // ---- Epilogue 2: + b2, store ----
    {
        int colB = nw * 32 + lr * 2;
#pragma unroll
        for (int mi = 0; mi < 4; mi++) {
            int r0 = rA + mi * 16 + lq;
            int gr0 = m0 + r0, gr1 = gr0 + 8;
#pragma unroll
            for (int nf = 0; nf < 4; nf++) {
                int col = colB + nf * 8;
                float2 bv = *(const float2*)(b2 + col);
                if (gr0 < N_NODES) {
                    float2 o = {acc2[mi][nf][0] + bv.x, acc2[mi][nf][1] + bv.y};
                    *(float2*)(out + (size_t)gr0 * ND + col) = o;
                }
                if (gr1 < N_NODES) {
                    float2 o = {acc2[mi][nf][2] + bv.x, acc2[mi][nf][3] + bv.y};
                    *(float2*)(out + (size_t)gr1 * ND + col) = o;
                }
            }
        }
    }
}

// ---------------- launch ----------------
extern "C" void kernel_launch(void* const* d_in, const int* in_sizes, int n_in,
                              void* d_out, int out_size) {
    const float* nodes   = (const float*)d_in[0];
    const float* edges   = (const float*)d_in[1];
    const int*   eindex  = (const int*)d_in[2];
    const int*   batch   = (const int*)d_in[3];
    const float* globals = (const float*)d_in[4];
    const float* W1      = (const float*)d_in[5];
    const float* b1      = (const float*)d_in[6];
    const float* W2      = (const float*)d_in[7];
    const float* b2      = (const float*)d_in[8];
    float*       out     = (float*)d_out;

    k_zero<<<(N_NODES * ED / 4 + 1023) / 1024, 1024>>>();
    k_scatter<<<(N_EDGES * 12) / 256, 256>>>(edges, eindex + N_EDGES);
    k_gu<<<NG, HID>>>(globals, W1, b1);
    k_w1t<<<192, 256>>>(W1);
    k_w2t<<<128, 256>>>(W2);

    cudaFuncSetAttribute(k_mlp_mma, cudaFuncAttributeMaxDynamicSharedMemorySize, SMEM_BYTES);
    k_mlp_mma<<<(N_NODES + 127) / 128, 256, SMEM_BYTES>>>(nodes, batch, b2, out);
}

// round 7
// speedup vs baseline: 1.9979x; 1.0537x over previous
#include <cuda_runtime.h>
#include <cuda_bf16.h>
#include <cstdint>

#define N_NODES 100000
#define N_EDGES 1600000
#define ND 128
#define ED 48
#define GD 64
#define NG 64
#define HID 256

// ---------------- device scratch ----------------
__device__ __align__(16) float g_agg[N_NODES * ED];
__device__ __align__(16) float g_gu[NG * HID];
// W1^T chunked blobs: [11 chunks][256 n][24 k] bf16 (16 data k + 8 pad)
__device__ __align__(16) __nv_bfloat16 g_w1t_h[11 * 256 * 24];
__device__ __align__(16) __nv_bfloat16 g_w1t_l[11 * 256 * 24];
// W2^T chunked blobs: [16 chunks][128 n][24 k]
__device__ __align__(16) __nv_bfloat16 g_w2t_h[16 * 128 * 24];
__device__ __align__(16) __nv_bfloat16 g_w2t_l[16 * 128 * 24];

// ---------------- helpers ----------------
__device__ __forceinline__ uint32_t smem_u32(const void* p) {
    return (uint32_t)__cvta_generic_to_shared(p);
}
__device__ __forceinline__ void cp16(char* dst, const char* src) {
    uint32_t s = smem_u32(dst);
    asm volatile("cp.async.cg.shared.global [%0], [%1], 16;" :: "r"(s), "l"(src));
}
#define CP_COMMIT asm volatile("cp.async.commit_group;")
__device__ __forceinline__ void cp_wait0() { asm volatile("cp.async.wait_group 0;"); }

__device__ __forceinline__ void ldsm4(uint32_t addr, uint32_t r[4]) {
    asm volatile("ldmatrix.sync.aligned.m8n8.x4.shared.b16 {%0,%1,%2,%3}, [%4];"
                 : "=r"(r[0]), "=r"(r[1]), "=r"(r[2]), "=r"(r[3]) : "r"(addr));
}
__device__ __forceinline__ void mma16816(float d[4], const uint32_t a[4],
                                         uint32_t b0, uint32_t b1) {
    asm volatile("mma.sync.aligned.m16n8k16.row.col.f32.bf16.bf16.f32 "
                 "{%0,%1,%2,%3}, {%4,%5,%6,%7}, {%8,%9}, {%0,%1,%2,%3};"
                 : "+f"(d[0]), "+f"(d[1]), "+f"(d[2]), "+f"(d[3])
                 : "r"(a[0]), "r"(a[1]), "r"(a[2]), "r"(a[3]), "r"(b0), "r"(b1));
}
__device__ __forceinline__ void st_pair(char* hiB, char* loB, int elemOff,
                                        float a, float b) {
    __nv_bfloat16 h0 = __float2bfloat16(a), h1 = __float2bfloat16(b);
    __nv_bfloat162 hp; hp.x = h0; hp.y = h1;
    __nv_bfloat162 lp;
    lp.x = __float2bfloat16(a - __bfloat162float(h0));
    lp.y = __float2bfloat16(b - __bfloat162float(h1));
    *(__nv_bfloat162*)(hiB + elemOff * 2) = hp;
    *(__nv_bfloat162*)(loB + elemOff * 2) = lp;
}

// ---------------- Kernel: zero agg ----------------
__global__ void k_zero() {
    int i = blockIdx.x * blockDim.x + threadIdx.x;
    if (i < (N_NODES * ED) / 4)
        reinterpret_cast<float4*>(g_agg)[i] = make_float4(0.f, 0.f, 0.f, 0.f);
}

// ---------------- Kernel: scatter-add (vector red) ----------------
__global__ void k_scatter(const float* __restrict__ edges,
                          const int* __restrict__ recv) {
    int idx = blockIdx.x * blockDim.x + threadIdx.x;
    if (idx >= N_EDGES * 12) return;
    int e = idx / 12;
    int c = idx - e * 12;
    float4 v = reinterpret_cast<const float4*>(edges)[idx];
    int r = recv[e];
    r = min(max(r, 0), N_NODES - 1);
    float* dst = g_agg + r * ED + c * 4;
    asm volatile("red.global.add.v4.f32 [%0], {%1,%2,%3,%4};"
                 :: "l"(dst), "f"(v.x), "f"(v.y), "f"(v.z), "f"(v.w) : "memory");
}

// ---------------- Kernel: gu = globals @ W1c + b1 (fp32) ----------------
__global__ void k_gu(const float* __restrict__ gg, const float* __restrict__ W1,
                     const float* __restrict__ b1) {
    __shared__ float sg[GD];
    int g = blockIdx.x, j = threadIdx.x;
    if (j < GD) sg[j] = gg[g * GD + j];
    __syncthreads();
    float acc = b1[j];
#pragma unroll
    for (int k = 0; k < GD; k++)
        acc = fmaf(sg[k], W1[(ND + ED + k) * HID + j], acc);
    g_gu[g * HID + j] = acc;
}

// ---------------- prep: W1^T hi/lo chunked [11][256][24] ----------------
__global__ void k_w1t(const float* __restrict__ W1) {
    int idx = blockIdx.x * 256 + threadIdx.x;   // 45056 = 176 k x 256 n
    int n = idx & 255, kg = idx >> 8;
    float v = W1[kg * HID + n];
    __nv_bfloat16 h = __float2bfloat16(v);
    __nv_bfloat16 l = __float2bfloat16(v - __bfloat162float(h));
    int chunk = kg >> 4, kc = kg & 15;
    int off = chunk * (256 * 24) + n * 24 + kc;
    g_w1t_h[off] = h;
    g_w1t_l[off] = l;
}

// ---------------- prep: W2^T hi/lo chunked [16][128][24] ----------------
__global__ void k_w2t(const float* __restrict__ W2) {
    int idx = blockIdx.x * 256 + threadIdx.x;   // 32768 = 256 k x 128 n
    int n = idx & 127, kg = idx >> 7;
    float v = W2[kg * ND + n];
    __nv_bfloat16 h = __float2bfloat16(v);
    __nv_bfloat16 l = __float2bfloat16(v - __bfloat162float(h));
    int chunk = kg >> 4, kc = kg & 15;
    int off = chunk * (128 * 24) + n * 24 + kc;
    g_w2t_h[off] = h;
    g_w2t_l[off] = l;
}

// ---------------- fused MLP via mma.sync bf16 hi/lo, 512 threads ----------------
// SMEM (bytes):
//  phase1: A_hi [0,47104) 128 x 184 elems (368B stride), A_lo [47104,94208)
//  phase2: H_hi [0,67584) 128 x 264 elems (528B stride), H_lo [67584,135168)
//  B at 135168: phase1 2 bufs x 24576 (hi 12288 | lo 12288)
//               phase2 2 bufs x 12288 (hi 6144  | lo 6144)
#define AH_OFF 0
#define AL_OFF 47104
#define HH_OFF 0
#define HL_OFF 67584
#define BB_OFF 135168
#define SMEM_BYTES 184320
#define SA_E 184   // A row stride (elems)
#define SH_E 264   // H row stride (elems)
#define NC1 11

__global__ void __launch_bounds__(512, 1) k_mlp_mma(
    const float* __restrict__ nodes, const int* __restrict__ batch,
    const float* __restrict__ b2, float* __restrict__ out) {
    extern __shared__ char smem[];
    const uint32_t sbase = smem_u32(smem);
    const int t = threadIdx.x;
    const int wid = t >> 5, lane = t & 31;
    const int m0 = blockIdx.x * 128;
    const int mw = wid >> 3;          // 0..1
    const int nw = wid & 7;           // 0..7
    const int rA = mw * 64;
    const int lq = lane >> 2;         // 0..7
    const int lr = lane & 3;          // 0..3

    auto copyB1 = [&](int kc) {
        char* dst = smem + BB_OFF + (kc & 1) * 24576;
        const char* sh = (const char*)g_w1t_h + kc * 12288;
        const char* sl = (const char*)g_w1t_l + kc * 12288;
        { int u = t;        if (u < 768) { cp16(dst + u * 16, sh + u * 16); cp16(dst + 12288 + u * 16, sl + u * 16); } }
        { int u = t + 512;  if (u < 768) { cp16(dst + u * 16, sh + u * 16); cp16(dst + 12288 + u * 16, sl + u * 16); } }
    };
    auto copyB2 = [&](int kc) {
        char* dst = smem + BB_OFF + (kc & 1) * 12288;
        const char* sh = (const char*)g_w2t_h + kc * 6144;
        const char* sl = (const char*)g_w2t_l + kc * 6144;
        if (t < 384) { cp16(dst + t * 16, sh + t * 16); cp16(dst + 6144 + t * 16, sl + t * 16); }
    };

    copyB1(0); CP_COMMIT;

    // ---- stage X = [nodes | agg] -> A hi/lo smem (K = 176 exact) ----
    {
        char* aH = smem + AH_OFF;
        char* aL = smem + AL_OFF;
#pragma unroll
        for (int i = 0; i < 8; i++) {             // nodes: 128 rows x 32 f4
            int f4 = t + i * 512;
            int row = f4 >> 5, q = f4 & 31;
            int gr = m0 + row;
            float4 v = make_float4(0.f, 0.f, 0.f, 0.f);
            if (gr < N_NODES) v = reinterpret_cast<const float4*>(nodes + (size_t)gr * ND)[q];
            int off = row * SA_E + q * 4;
            st_pair(aH, aL, off,     v.x, v.y);
            st_pair(aH, aL, off + 2, v.z, v.w);
        }
#pragma unroll
        for (int i = 0; i < 3; i++) {             // agg: 128 rows x 12 f4
            int f4 = t + i * 512;
            int row = f4 / 12, q = f4 - row * 12;
            int gr = m0 + row;
            float4 v = make_float4(0.f, 0.f, 0.f, 0.f);
            if (gr < N_NODES) v = reinterpret_cast<const float4*>(g_agg + (size_t)gr * ED)[q];
            int off = row * SA_E + 128 + q * 4;
            st_pair(aH, aL, off,     v.x, v.y);
            st_pair(aH, aL, off + 2, v.z, v.w);
        }
    }

    // ldmatrix per-lane bases
    const uint32_t aRowH = sbase + AH_OFF + (rA + (lane & 15)) * (SA_E * 2) + (lane >> 4) * 16;
    const uint32_t aRowL = aRowH + (AL_OFF - AH_OFF);
    const uint32_t bRow1 = (nw * 32 + (lane & 15)) * 48 + (lane >> 4) * 16;
    const uint32_t bRow2 = (nw * 16 + (lane & 15)) * 48 + (lane >> 4) * 16;

    // ---------------- Phase 1: warp tile 64x32, 11 chunks ----------------
    float acc[4][4][4];
#pragma unroll
    for (int a = 0; a < 4; a++)
#pragma unroll
        for (int b = 0; b < 4; b++)
#pragma unroll
            for (int c = 0; c < 4; c++) acc[a][b][c] = 0.f;

    for (int kc = 0; kc < NC1; ++kc) {
        cp_wait0();
        __syncthreads();
        if (kc < NC1 - 1) { copyB1(kc + 1); CP_COMMIT; }

        uint32_t bufH = sbase + BB_OFF + (kc & 1) * 24576;
        uint32_t bufL = bufH + 12288;
        uint32_t ah[4][4], al[4][4], bh[2][4], bl[2][4];
#pragma unroll
        for (int mi = 0; mi < 4; mi++) {
            ldsm4(aRowH + mi * (16 * SA_E * 2) + kc * 32, ah[mi]);
            ldsm4(aRowL + mi * (16 * SA_E * 2) + kc * 32, al[mi]);
        }
#pragma unroll
        for (int j = 0; j < 2; j++) {
            ldsm4(bufH + bRow1 + j * 768, bh[j]);
            ldsm4(bufL + bRow1 + j * 768, bl[j]);
        }
#pragma unroll
        for (int mi = 0; mi < 4; mi++)
#pragma unroll
            for (int j = 0; j < 2; j++) {
                mma16816(acc[mi][2 * j],     ah[mi], bh[j][0], bh[j][2]);
                mma16816(acc[mi][2 * j],     ah[mi], bl[j][0], bl[j][2]);
                mma16816(acc[mi][2 * j],     al[mi], bh[j][0], bh[j][2]);
                mma16816(acc[mi][2 * j + 1], ah[mi], bh[j][1], bh[j][3]);
                mma16816(acc[mi][2 * j + 1], ah[mi], bl[j][1], bl[j][3]);
                mma16816(acc[mi][2 * j + 1], al[mi], bh[j][1], bh[j][3]);
            }
    }
    __syncthreads();          // all A reads done; B1 buffers drained

    copyB2(0); CP_COMMIT;     // overlaps epilogue 1

    // ---- Epilogue 1: +gu[batch], ReLU, hi/lo -> H smem ----
    {
        char* hH = smem + HH_OFF;
        char* hL = smem + HL_OFF;
        int colB = nw * 32 + lr * 2;
#pragma unroll
        for (int mi = 0; mi < 4; mi++) {
            int r0 = rA + mi * 16 + lq;
            int r1 = r0 + 8;
            int g0 = batch[min(m0 + r0, N_NODES - 1)];
            int g1 = batch[min(m0 + r1, N_NODES - 1)];
            g0 = min(max(g0, 0), NG - 1);
            g1 = min(max(g1, 0), NG - 1);
            const float* gu0 = g_gu + g0 * HID;
            const float* gu1 = g_gu + g1 * HID;
#pragma unroll
            for (int nf = 0; nf < 4; nf++) {
                int col = colB + nf * 8;
                float2 u0 = *(const float2*)(gu0 + col);
                float2 u1 = *(const float2*)(gu1 + col);
                float v00 = fmaxf(acc[mi][nf][0] + u0.x, 0.f);
                float v01 = fmaxf(acc[mi][nf][1] + u0.y, 0.f);
                float v10 = fmaxf(acc[mi][nf][2] + u1.x, 0.f);
                float v11 = fmaxf(acc[mi][nf][3] + u1.y, 0.f);
                st_pair(hH, hL, r0 * SH_E + col, v00, v01);
                st_pair(hH, hL, r1 * SH_E + col, v10, v11);
            }
        }
    }

    // ---------------- Phase 2: warp tile 64x16, 16 chunks ----------------
    const uint32_t hRowH = sbase + HH_OFF + (rA + (lane & 15)) * (SH_E * 2) + (lane >> 4) * 16;
    const uint32_t hRowL = hRowH + (HL_OFF - HH_OFF);

    float acc2[4][2][4];
#pragma unroll
    for (int a = 0; a < 4; a++)
#pragma unroll
        for (int b = 0; b < 2; b++)
#pragma unroll
            for (int c = 0; c < 4; c++) acc2[a][b][c] = 0.f;

    for (int kc = 0; kc < 16; ++kc) {
        cp_wait0();
        __syncthreads();      // H writes visible (kc=0) + buffer reuse safety
        if (kc < 15) { copyB2(kc + 1); CP_COMMIT; }

        uint32_t bufH = sbase + BB_OFF + (kc & 1) * 12288;
        uint32_t bufL = bufH + 6144;
        uint32_t ah[4][4], al[4][4], bh[4], bl[4];
#pragma unroll
        for (int mi = 0; mi < 4; mi++) {
            ldsm4(hRowH + mi * (16 * SH_E * 2) + kc * 32, ah[mi]);
            ldsm4(hRowL + mi * (16 * SH_E * 2) + kc * 32, al[mi]);
        }
        ldsm4(bufH + bRow2, bh);
        ldsm4(bufL + bRow2, bl);
#pragma unroll
        for (int mi = 0; mi < 4; mi++) {
            mma16816(acc2[mi][0], ah[mi], bh[0], bh[2]);
            mma16816(acc2[mi][0], ah[mi], bl[0], bl[2]);
            mma16816(acc2[mi][0], al[mi], bh[0], bh[2]);
            mma16816(acc2[mi][1], ah[mi], bh[1], bh[3]);
            mma16816(acc2[mi][1], ah[mi], bl[1], bl[3]);
            mma16816(acc2[mi][1], al[mi], bh[1], bh[3]);
        }
    }

    // ---- Epilogue 2: + b2, store ----
    {
        int colB = nw * 16 + lr * 2;
#pragma unroll
        for (int mi = 0; mi < 4; mi++) {
            int r0 = rA + mi * 16 + lq;
            int gr0 = m0 + r0, gr1 = gr0 + 8;
#pragma unroll
            for (int nf = 0; nf < 2; nf++) {
                int col = colB + nf * 8;
                float2 bv = *(const float2*)(b2 + col);
                if (gr0 < N_NODES) {
                    float2 o = {acc2[mi][nf][0] + bv.x, acc2[mi][nf][1] + bv.y};
                    *(float2*)(out + (size_t)gr0 * ND + col) = o;
                }
                if (gr1 < N_NODES) {
                    float2 o = {acc2[mi][nf][2] + bv.x, acc2[mi][nf][3] + bv.y};
                    *(float2*)(out + (size_t)gr1 * ND + col) = o;
                }
            }
        }
    }
}

// ---------------- launch ----------------
extern "C" void kernel_launch(void* const* d_in, const int* in_sizes, int n_in,
                              void* d_out, int out_size) {
    const float* nodes   = (const float*)d_in[0];
    const float* edges   = (const float*)d_in[1];
    const int*   eindex  = (const int*)d_in[2];
    const int*   batch   = (const int*)d_in[3];
    const float* globals = (const float*)d_in[4];
    const float* W1      = (const float*)d_in[5];
    const float* b1      = (const float*)d_in[6];
    const float* W2      = (const float*)d_in[7];
    const float* b2      = (const float*)d_in[8];
    float*       out     = (float*)d_out;

    k_zero<<<(N_NODES * ED / 4 + 1023) / 1024, 1024>>>();
    k_scatter<<<(N_EDGES * 12) / 256, 256>>>(edges, eindex + N_EDGES);
    k_gu<<<NG, HID>>>(globals, W1, b1);
    k_w1t<<<176, 256>>>(W1);
    k_w2t<<<128, 256>>>(W2);

    cudaFuncSetAttribute(k_mlp_mma, cudaFuncAttributeMaxDynamicSharedMemorySize, SMEM_BYTES);
    k_mlp_mma<<<(N_NODES + 127) / 128, 512, SMEM_BYTES>>>(nodes, batch, b2, out);
}

// round 9
// speedup vs baseline: 2.3463x; 1.1744x over previous
#include <cuda_runtime.h>
#include <cuda_bf16.h>
#include <cstdint>

#define N_NODES 100000
#define N_EDGES 1600000
#define ND 128
#define ED 48
#define GD 64
#define NG 64
#define HID 256

// ---------------- device scratch ----------------
__device__ __align__(16) float g_agg[N_NODES * ED];
__device__ __align__(16) float g_gu[NG * HID];
// W1^T chunked blobs: [11 chunks][256 n][24 k] bf16 (16 data k + 8 pad)
__device__ __align__(16) __nv_bfloat16 g_w1t_h[11 * 256 * 24];
__device__ __align__(16) __nv_bfloat16 g_w1t_l[11 * 256 * 24];
// W2^T chunked blobs: [16 chunks][128 n][24 k]
__device__ __align__(16) __nv_bfloat16 g_w2t_h[16 * 128 * 24];
__device__ __align__(16) __nv_bfloat16 g_w2t_l[16 * 128 * 24];

// ---------------- helpers ----------------
__device__ __forceinline__ uint32_t smem_u32(const void* p) {
    return (uint32_t)__cvta_generic_to_shared(p);
}
__device__ __forceinline__ void cp16(char* dst, const char* src) {
    uint32_t s = smem_u32(dst);
    asm volatile("cp.async.cg.shared.global [%0], [%1], 16;" :: "r"(s), "l"(src));
}
#define CP_COMMIT asm volatile("cp.async.commit_group;")
__device__ __forceinline__ void cp_wait0() { asm volatile("cp.async.wait_group 0;"); }

__device__ __forceinline__ void ldsm4(uint32_t addr, uint32_t r[4]) {
    asm volatile("ldmatrix.sync.aligned.m8n8.x4.shared.b16 {%0,%1,%2,%3}, [%4];"
                 : "=r"(r[0]), "=r"(r[1]), "=r"(r[2]), "=r"(r[3]) : "r"(addr));
}
__device__ __forceinline__ void mma16816(float d[4], const uint32_t a[4],
                                         uint32_t b0, uint32_t b1) {
    asm volatile("mma.sync.aligned.m16n8k16.row.col.f32.bf16.bf16.f32 "
                 "{%0,%1,%2,%3}, {%4,%5,%6,%7}, {%8,%9}, {%0,%1,%2,%3};"
                 : "+f"(d[0]), "+f"(d[1]), "+f"(d[2]), "+f"(d[3])
                 : "r"(a[0]), "r"(a[1]), "r"(a[2]), "r"(a[3]), "r"(b0), "r"(b1));
}
__device__ __forceinline__ void st_pair(char* hiB, char* loB, int elemOff,
                                        float a, float b) {
    __nv_bfloat16 h0 = __float2bfloat16(a), h1 = __float2bfloat16(b);
    __nv_bfloat162 hp; hp.x = h0; hp.y = h1;
    __nv_bfloat162 lp;
    lp.x = __float2bfloat16(a - __bfloat162float(h0));
    lp.y = __float2bfloat16(b - __bfloat162float(h1));
    *(__nv_bfloat162*)(hiB + elemOff * 2) = hp;
    *(__nv_bfloat162*)(loB + elemOff * 2) = lp;
}

// ---------------- Kernel: scatter-add (vector red) ----------------
__global__ void k_scatter(const float* __restrict__ edges,
                          const int* __restrict__ recv) {
    int idx = blockIdx.x * blockDim.x + threadIdx.x;
    if (idx >= N_EDGES * 12) return;
    int e = idx / 12;
    int c = idx - e * 12;
    float4 v = reinterpret_cast<const float4*>(edges)[idx];
    int r = recv[e];
    r = min(max(r, 0), N_NODES - 1);
    float* dst = g_agg + r * ED + c * 4;
    asm volatile("red.global.add.v4.f32 [%0], {%1,%2,%3,%4};"
                 :: "l"(dst), "f"(v.x), "f"(v.y), "f"(v.z), "f"(v.w) : "memory");
}

// ---------------- fused prep: zero agg | W1^T blobs | W2^T blobs | gu ----------------
// grid = 4688 (zero) + 176 (w1t) + 128 (w2t) + 64 (gu) = 5056 blocks x 256 thr
__global__ void k_prep(const float* __restrict__ gg, const float* __restrict__ W1,
                       const float* __restrict__ b1, const float* __restrict__ W2) {
    __shared__ float sg[GD];
    int b = blockIdx.x, t = threadIdx.x;
    if (b < 4688) {                       // zero g_agg (1.2M float4)
        int i = b * 256 + t;
        if (i < (N_NODES * ED) / 4)
            reinterpret_cast<float4*>(g_agg)[i] = make_float4(0.f, 0.f, 0.f, 0.f);
    } else if (b < 4864) {                // W1^T hi/lo: kg = block, n = t
        int kg = b - 4688, n = t;
        float v = W1[kg * HID + n];
        __nv_bfloat16 h = __float2bfloat16(v);
        __nv_bfloat16 l = __float2bfloat16(v - __bfloat162float(h));
        int off = (kg >> 4) * (256 * 24) + n * 24 + (kg & 15);
        g_w1t_h[off] = h;
        g_w1t_l[off] = l;
    } else if (b < 4992) {                // W2^T hi/lo
        int idx = (b - 4864) * 256 + t;
        int n = idx & 127, kg = idx >> 7;
        float v = W2[kg * ND + n];
        __nv_bfloat16 h = __float2bfloat16(v);
        __nv_bfloat16 l = __float2bfloat16(v - __bfloat162float(h));
        int off = (kg >> 4) * (128 * 24) + n * 24 + (kg & 15);
        g_w2t_h[off] = h;
        g_w2t_l[off] = l;
    } else {                              // gu = globals @ W1c + b1
        int g = b - 4992, j = t;
        if (j < GD) sg[j] = gg[g * GD + j];
        __syncthreads();
        float acc = b1[j];
#pragma unroll
        for (int k = 0; k < GD; k++)
            acc = fmaf(sg[k], W1[(ND + ED + k) * HID + j], acc);
        g_gu[g * HID + j] = acc;
    }
}

// ---------------- fused MLP: 64 rows/block, 256 thr, 2 CTAs/SM ----------------
// SMEM (bytes):
//  phase1: A_hi [0,23552) 64 x 184 elems (368B), A_lo [23552,47104)
//          B1   [47104,96256) 2 bufs x 24576 (hi 12288 | lo 12288)
//  phase2: H_hi [0,33792) 64 x 264 elems (528B), H_lo [33792,67584)
//          B2   [67584,92160) 2 bufs x 12288 (hi 6144 | lo 6144)
#define AH_OFF 0
#define AL_OFF 23552
#define B1_OFF 47104
#define HH_OFF 0
#define HL_OFF 33792
#define B2_OFF 67584
#define SMEM_BYTES 96256
#define SA_E 184
#define SH_E 264
#define NC1 11

__global__ void __launch_bounds__(256, 2) k_mlp_mma(
    const float* __restrict__ nodes, const int* __restrict__ batch,
    const float* __restrict__ b2, float* __restrict__ out) {
    extern __shared__ char smem[];
    const uint32_t sbase = smem_u32(smem);
    const int t = threadIdx.x;
    const int wid = t >> 5, lane = t & 31;
    const int m0 = blockIdx.x * 64;
    const int mw = wid >> 2;          // 0..1 -> 32-row band
    const int nw = wid & 3;           // 0..3
    const int rA = mw * 32;
    const int lq = lane >> 2;         // 0..7
    const int lr = lane & 3;          // 0..3

    auto copyB1 = [&](int kc) {
        char* dst = smem + B1_OFF + (kc & 1) * 24576;
        const char* sh = (const char*)g_w1t_h + kc * 12288;
        const char* sl = (const char*)g_w1t_l + kc * 12288;
#pragma unroll
        for (int i = 0; i < 3; i++) {
            int u = (t + i * 256) * 16;
            cp16(dst + u, sh + u);
            cp16(dst + 12288 + u, sl + u);
        }
    };
    auto copyB2 = [&](int kc) {
        char* dst = smem + B2_OFF + (kc & 1) * 12288;
        const char* sh = (const char*)g_w2t_h + kc * 6144;
        const char* sl = (const char*)g_w2t_l + kc * 6144;
#pragma unroll
        for (int i = 0; i < 2; i++) {
            int u = t + i * 256;
            if (u < 384) {
                cp16(dst + u * 16, sh + u * 16);
                cp16(dst + 6144 + u * 16, sl + u * 16);
            }
        }
    };

    copyB1(0); CP_COMMIT;

    // ---- stage X = [nodes | agg] -> A hi/lo smem (K = 176 exact) ----
    {
        char* aH = smem + AH_OFF;
        char* aL = smem + AL_OFF;
#pragma unroll
        for (int i = 0; i < 8; i++) {             // nodes: 64 rows x 32 f4
            int f4 = t + i * 256;
            int row = f4 >> 5, q = f4 & 31;
            int gr = m0 + row;
            float4 v = make_float4(0.f, 0.f, 0.f, 0.f);
            if (gr < N_NODES) v = reinterpret_cast<const float4*>(nodes + (size_t)gr * ND)[q];
            int off = row * SA_E + q * 4;
            st_pair(aH, aL, off,     v.x, v.y);
            st_pair(aH, aL, off + 2, v.z, v.w);
        }
#pragma unroll
        for (int i = 0; i < 3; i++) {             // agg: 64 rows x 12 f4
            int f4 = t + i * 256;
            if (f4 < 768) {
                int row = f4 / 12, q = f4 - row * 12;
                int gr = m0 + row;
                float4 v = make_float4(0.f, 0.f, 0.f, 0.f);
                if (gr < N_NODES) v = reinterpret_cast<const float4*>(g_agg + (size_t)gr * ED)[q];
                int off = row * SA_E + 128 + q * 4;
                st_pair(aH, aL, off,     v.x, v.y);
                st_pair(aH, aL, off + 2, v.z, v.w);
            }
        }
    }

    // ldmatrix per-lane bases
    const uint32_t aRowH = sbase + AH_OFF + (rA + (lane & 15)) * (SA_E * 2) + (lane >> 4) * 16;
    const uint32_t aRowL = aRowH + (AL_OFF - AH_OFF);
    const uint32_t bRow1 = (nw * 64 + (lane & 15)) * 48 + (lane >> 4) * 16;
    const uint32_t bRow2 = (nw * 32 + (lane & 15)) * 48 + (lane >> 4) * 16;

    // ---------------- Phase 1: warp tile 32x64, 11 chunks ----------------
    float acc[2][8][4];
#pragma unroll
    for (int a = 0; a < 2; a++)
#pragma unroll
        for (int b = 0; b < 8; b++)
#pragma unroll
            for (int c = 0; c < 4; c++) acc[a][b][c] = 0.f;

    for (int kc = 0; kc < NC1; ++kc) {
        cp_wait0();
        __syncthreads();
        if (kc < NC1 - 1) { copyB1(kc + 1); CP_COMMIT; }

        uint32_t bufH = sbase + B1_OFF + (kc & 1) * 24576;
        uint32_t bufL = bufH + 12288;
        uint32_t ah[2][4], al[2][4];
#pragma unroll
        for (int mi = 0; mi < 2; mi++) {
            ldsm4(aRowH + mi * (16 * SA_E * 2) + kc * 32, ah[mi]);
            ldsm4(aRowL + mi * (16 * SA_E * 2) + kc * 32, al[mi]);
        }
#pragma unroll
        for (int j = 0; j < 4; j++) {
            uint32_t bh[4], bl[4];
            ldsm4(bufH + bRow1 + j * 768, bh);
            ldsm4(bufL + bRow1 + j * 768, bl);
#pragma unroll
            for (int mi = 0; mi < 2; mi++) {
                mma16816(acc[mi][2 * j],     ah[mi], bh[0], bh[2]);
                mma16816(acc[mi][2 * j],     ah[mi], bl[0], bl[2]);
                mma16816(acc[mi][2 * j],     al[mi], bh[0], bh[2]);
                mma16816(acc[mi][2 * j + 1], ah[mi], bh[1], bh[3]);
                mma16816(acc[mi][2 * j + 1], ah[mi], bl[1], bl[3]);
                mma16816(acc[mi][2 * j + 1], al[mi], bh[1], bh[3]);
            }
        }
    }
    __syncthreads();          // A reads done; B1 dead -> H/B2 regions free

    copyB2(0); CP_COMMIT;     // overlaps epilogue 1

    // ---- Epilogue 1: +gu[batch], ReLU, hi/lo -> H smem ----
    {
        char* hH = smem + HH_OFF;
        char* hL = smem + HL_OFF;
        int colB = nw * 64 + lr * 2;
#pragma unroll
        for (int mi = 0; mi < 2; mi++) {
            int r0 = rA + mi * 16 + lq;
            int r1 = r0 + 8;
            int g0 = batch[min(m0 + r0, N_NODES - 1)];
            int g1 = batch[min(m0 + r1, N_NODES - 1)];
            g0 = min(max(g0, 0), NG - 1);
            g1 = min(max(g1, 0), NG - 1);
            const float* gu0 = g_gu + g0 * HID;
            const float* gu1 = g_gu + g1 * HID;
#pragma unroll
            for (int nf = 0; nf < 8; nf++) {
                int col = colB + nf * 8;
                float2 u0 = *(const float2*)(gu0 + col);
                float2 u1 = *(const float2*)(gu1 + col);
                float v00 = fmaxf(acc[mi][nf][0] + u0.x, 0.f);
                float v01 = fmaxf(acc[mi][nf][1] + u0.y, 0.f);
                float v10 = fmaxf(acc[mi][nf][2] + u1.x, 0.f);
                float v11 = fmaxf(acc[mi][nf][3] + u1.y, 0.f);
                st_pair(hH, hL, r0 * SH_E + col, v00, v01);
                st_pair(hH, hL, r1 * SH_E + col, v10, v11);
            }
        }
    }

    // ---------------- Phase 2: warp tile 32x32, 16 chunks ----------------
    const uint32_t hRowH = sbase + HH_OFF + (rA + (lane & 15)) * (SH_E * 2) + (lane >> 4) * 16;
    const uint32_t hRowL = hRowH + (HL_OFF - HH_OFF);

    float acc2[2][4][4];
#pragma unroll
    for (int a = 0; a < 2; a++)
#pragma unroll
        for (int b = 0; b < 4; b++)
#pragma unroll
            for (int c = 0; c < 4; c++) acc2[a][b][c] = 0.f;

    for (int kc = 0; kc < 16; ++kc) {
        cp_wait0();
        __syncthreads();      // H visible (kc=0) + buffer reuse safety
        if (kc < 15) { copyB2(kc + 1); CP_COMMIT; }

        uint32_t bufH = sbase + B2_OFF + (kc & 1) * 12288;
        uint32_t bufL = bufH + 6144;
        uint32_t ah[2][4], al[2][4];
#pragma unroll
        for (int mi = 0; mi < 2; mi++) {
            ldsm4(hRowH + mi * (16 * SH_E * 2) + kc * 32, ah[mi]);
            ldsm4(hRowL + mi * (16 * SH_E * 2) + kc * 32, al[mi]);
        }
#pragma unroll
        for (int j = 0; j < 2; j++) {
            uint32_t bh[4], bl[4];
            ldsm4(bufH + bRow2 + j * 768, bh);
            ldsm4(bufL + bRow2 + j * 768, bl);
#pragma unroll
            for (int mi = 0; mi < 2; mi++) {
                mma16816(acc2[mi][2 * j],     ah[mi], bh[0], bh[2]);
                mma16816(acc2[mi][2 * j],     ah[mi], bl[0], bl[2]);
                mma16816(acc2[mi][2 * j],     al[mi], bh[0], bh[2]);
                mma16816(acc2[mi][2 * j + 1], ah[mi], bh[1], bh[3]);
                mma16816(acc2[mi][2 * j + 1], ah[mi], bl[1], bl[3]);
                mma16816(acc2[mi][2 * j + 1], al[mi], bh[1], bh[3]);
            }
        }
    }

    // ---- Epilogue 2: + b2, store ----
    {
        int colB = nw * 32 + lr * 2;
#pragma unroll
        for (int mi = 0; mi < 2; mi++) {
            int r0 = rA + mi * 16 + lq;
            int gr0 = m0 + r0, gr1 = gr0 + 8;
#pragma unroll
            for (int nf = 0; nf < 4; nf++) {
                int col = colB + nf * 8;
                float2 bv = *(const float2*)(b2 + col);
                if (gr0 < N_NODES) {
                    float2 o = {acc2[mi][nf][0] + bv.x, acc2[mi][nf][1] + bv.y};
                    *(float2*)(out + (size_t)gr0 * ND + col) = o;
                }
                if (gr1 < N_NODES) {
                    float2 o = {acc2[mi][nf][2] + bv.x, acc2[mi][nf][3] + bv.y};
                    *(float2*)(out + (size_t)gr1 * ND + col) = o;
                }
            }
        }
    }
}

// ---------------- launch ----------------
extern "C" void kernel_launch(void* const* d_in, const int* in_sizes, int n_in,
                              void* d_out, int out_size) {
    const float* nodes   = (const float*)d_in[0];
    const float* edges   = (const float*)d_in[1];
    const int*   eindex  = (const int*)d_in[2];
    const int*   batch   = (const int*)d_in[3];
    const float* globals = (const float*)d_in[4];
    const float* W1      = (const float*)d_in[5];
    const float* b1      = (const float*)d_in[6];
    const float* W2      = (const float*)d_in[7];
    const float* b2      = (const float*)d_in[8];
    float*       out     = (float*)d_out;

    k_prep<<<5056, 256>>>(globals, W1, b1, W2);
    k_scatter<<<(N_EDGES * 12) / 256, 256>>>(edges, eindex + N_EDGES);

    cudaFuncSetAttribute(k_mlp_mma, cudaFuncAttributeMaxDynamicSharedMemorySize, SMEM_BYTES);
    k_mlp_mma<<<(N_NODES + 63) / 64, 256, SMEM_BYTES>>>(nodes, batch, b2, out);
}

// round 11
// speedup vs baseline: 2.5325x; 1.0794x over previous
#include <cuda_runtime.h>
#include <cuda_bf16.h>
#include <cstdint>

#define N_NODES 100000
#define N_EDGES 1600000
#define ND 128
#define ED 48
#define GD 64
#define NG 64
#define HID 256

// ---------------- device scratch ----------------
__device__ __align__(16) float g_agg[N_NODES * ED];
__device__ __align__(16) float g_gu[NG * HID];
// W1^T tf32 blob: [11 chunks][256 n][16 k] (k-permuted), fp32 storage
__device__ __align__(16) float g_w1t[11 * 256 * 16];
// W2^T tf32 blob: [16 chunks][128 n][16 k]
__device__ __align__(16) float g_w2t[16 * 128 * 16];

// ---------------- helpers ----------------
__device__ __forceinline__ uint32_t smem_u32(const void* p) {
    return (uint32_t)__cvta_generic_to_shared(p);
}
__device__ __forceinline__ void cp16(char* dst, const char* src) {
    uint32_t s = smem_u32(dst);
    asm volatile("cp.async.cg.shared.global [%0], [%1], 16;" :: "r"(s), "l"(src));
}
#define CP_COMMIT asm volatile("cp.async.commit_group;")
__device__ __forceinline__ void cp_wait0() { asm volatile("cp.async.wait_group 0;"); }

__device__ __forceinline__ uint32_t f2tf(float f) {
    uint32_t r;
    asm("cvt.rna.tf32.f32 %0, %1;" : "=r"(r) : "f"(f));
    return r;
}
__device__ __forceinline__ void mma_tf32(float d[4], uint32_t a0, uint32_t a1,
                                         uint32_t a2, uint32_t a3,
                                         uint32_t b0, uint32_t b1) {
    asm volatile("mma.sync.aligned.m16n8k8.row.col.f32.tf32.tf32.f32 "
                 "{%0,%1,%2,%3}, {%4,%5,%6,%7}, {%8,%9}, {%0,%1,%2,%3};"
                 : "+f"(d[0]), "+f"(d[1]), "+f"(d[2]), "+f"(d[3])
                 : "r"(a0), "r"(a1), "r"(a2), "r"(a3), "r"(b0), "r"(b1));
}
__device__ __forceinline__ uint4 lds128(uint32_t addr) {
    uint4 v;
    asm volatile("ld.shared.v4.b32 {%0,%1,%2,%3}, [%4];"
                 : "=r"(v.x), "=r"(v.y), "=r"(v.z), "=r"(v.w) : "r"(addr));
    return v;
}

// k-permutation within a 16-chunk: logical k (4q+r) stored at 4r+q.
// Stored col for logical col c:
__device__ __forceinline__ int kperm(int c) {
    return (c & ~15) + 4 * (c & 3) + ((c >> 2) & 3);
}

// ---------------- Kernel: scatter-add (vector red) ----------------
__global__ void k_scatter(const float* __restrict__ edges,
                          const int* __restrict__ recv) {
    int idx = blockIdx.x * blockDim.x + threadIdx.x;
    if (idx >= N_EDGES * 12) return;
    int e = idx / 12;
    int c = idx - e * 12;
    float4 v = reinterpret_cast<const float4*>(edges)[idx];
    int r = recv[e];
    r = min(max(r, 0), N_NODES - 1);
    float* dst = g_agg + r * ED + c * 4;
    asm volatile("red.global.add.v4.f32 [%0], {%1,%2,%3,%4};"
                 :: "l"(dst), "f"(v.x), "f"(v.y), "f"(v.z), "f"(v.w) : "memory");
}

// ---------------- fused prep: zero agg | W1^T | W2^T | gu ----------------
// grid = 4688 + 176 + 128 + 64 = 5056 blocks x 256 thr
__global__ void k_prep(const float* __restrict__ gg, const float* __restrict__ W1,
                       const float* __restrict__ b1, const float* __restrict__ W2) {
    __shared__ float sg[GD];
    int b = blockIdx.x, t = threadIdx.x;
    if (b < 4688) {                       // zero g_agg
        int i = b * 256 + t;
        if (i < (N_NODES * ED) / 4)
            reinterpret_cast<float4*>(g_agg)[i] = make_float4(0.f, 0.f, 0.f, 0.f);
    } else if (b < 4864) {                // W1^T tf32 blob [11][256][16]
        int idx = (b - 4688) * 256 + t;   // 45056
        int p = idx & 15, n = (idx >> 4) & 255, chunk = idx >> 12;
        int kg = chunk * 16 + 4 * (p & 3) + (p >> 2);
        g_w1t[idx] = __uint_as_float(f2tf(W1[kg * HID + n]));
    } else if (b < 4992) {                // W2^T tf32 blob [16][128][16]
        int idx = (b - 4864) * 256 + t;   // 32768
        int p = idx & 15, n = (idx >> 4) & 127, chunk = idx >> 11;
        int kg = chunk * 16 + 4 * (p & 3) + (p >> 2);
        g_w2t[idx] = __uint_as_float(f2tf(W2[kg * ND + n]));
    } else {                              // gu = globals @ W1c + b1 (fp32)
        int g = b - 4992, j = t;
        if (j < GD) sg[j] = gg[g * GD + j];
        __syncthreads();
        float acc = b1[j];
#pragma unroll
        for (int k = 0; k < GD; k++)
            acc = fmaf(sg[k], W1[(ND + ED + k) * HID + j], acc);
        g_gu[g * HID + j] = acc;
    }
}

// ---------------- fused MLP: tf32 mma, 64 rows/block, 2 CTAs/SM ----------------
// SMEM (bytes):
//  phase1: A  [0, 45056)  64 x 176 fp32 (704B stride, k-permuted)
//          B1 [46080, 78848)  2 bufs x 16384 (256n x 16k fp32)
//  phase2: H  [0, 69632)  64 x 272-stride fp32 (1088B, k-permuted, cols 0..255)
//          B2 [78848, 95232)  2 bufs x 8192 (128n x 16k fp32)
#define A_OFF  0
#define B1_OFF 46080
#define H_OFF  0
#define B2_OFF 78848
#define SMEM_BYTES 95232
#define SA_E 176
#define SH_E 272
#define NC1 11

__global__ void __launch_bounds__(256, 2) k_mlp_mma(
    const float* __restrict__ nodes, const int* __restrict__ batch,
    const float* __restrict__ b2, float* __restrict__ out) {
    extern __shared__ char smem[];
    const uint32_t sbase = smem_u32(smem);
    const int t = threadIdx.x;
    const int wid = t >> 5, lane = t & 31;
    const int m0 = blockIdx.x * 64;
    const int mw = wid >> 2;          // 0..1 -> 32-row band
    const int nw = wid & 3;           // 0..3
    const int rA = mw * 32;
    const int lq = lane >> 2;         // 0..7
    const int lr = lane & 3;          // 0..3

    auto copyB1 = [&](int kc) {
        char* dst = smem + B1_OFF + (kc & 1) * 16384;
        const char* src = (const char*)g_w1t + kc * 16384;
#pragma unroll
        for (int i = 0; i < 4; i++) {
            int u = (t + i * 256) * 16;
            cp16(dst + u, src + u);
        }
    };
    auto copyB2 = [&](int kc) {
        char* dst = smem + B2_OFF + (kc & 1) * 8192;
        const char* src = (const char*)g_w2t + kc * 8192;
#pragma unroll
        for (int i = 0; i < 2; i++) {
            int u = (t + i * 256) * 16;
            cp16(dst + u, src + u);
        }
    };

    copyB1(0); CP_COMMIT;

    // ---- stage X = [nodes | agg] -> A smem (tf32 bits, k-permuted) ----
    {
        float* A = (float*)(smem + A_OFF);
#pragma unroll
        for (int i = 0; i < 8; i++) {             // nodes: 64 rows x 32 quads
            int f4 = t + i * 256;
            int row = f4 >> 5, qq = f4 & 31;
            int gr = m0 + row;
            float4 v = make_float4(0.f, 0.f, 0.f, 0.f);
            if (gr < N_NODES) v = reinterpret_cast<const float4*>(nodes + (size_t)gr * ND)[qq];
            int base = row * SA_E + (qq >> 2) * 16 + (qq & 3);
            A[base]      = __uint_as_float(f2tf(v.x));
            A[base + 4]  = __uint_as_float(f2tf(v.y));
            A[base + 8]  = __uint_as_float(f2tf(v.z));
            A[base + 12] = __uint_as_float(f2tf(v.w));
        }
#pragma unroll
        for (int i = 0; i < 3; i++) {             // agg: 64 rows x 12 quads (k 128..175)
            int f4 = t + i * 256;
            if (f4 < 768) {
                int row = f4 / 12, j = f4 - row * 12;
                int gr = m0 + row;
                float4 v = make_float4(0.f, 0.f, 0.f, 0.f);
                if (gr < N_NODES) v = reinterpret_cast<const float4*>(g_agg + (size_t)gr * ED)[j];
                int qq = 32 + j;
                int base = row * SA_E + (qq >> 2) * 16 + (qq & 3);
                A[base]      = __uint_as_float(f2tf(v.x));
                A[base + 4]  = __uint_as_float(f2tf(v.y));
                A[base + 8]  = __uint_as_float(f2tf(v.z));
                A[base + 12] = __uint_as_float(f2tf(v.w));
            }
        }
    }

    // per-lane fragment addresses (bytes)
    const uint32_t aBase = sbase + A_OFF + (rA + lq) * (SA_E * 4) + lr * 16;
    const uint32_t b1Base = sbase + B1_OFF + (nw * 64 + lq) * 64 + lr * 16;
    const uint32_t b2Base = sbase + B2_OFF + (nw * 32 + lq) * 64 + lr * 16;

    // ---------------- Phase 1: warp tile 32x64, 11 chunks ----------------
    float acc[2][8][4];
#pragma unroll
    for (int a = 0; a < 2; a++)
#pragma unroll
        for (int b = 0; b < 8; b++)
#pragma unroll
            for (int c = 0; c < 4; c++) acc[a][b][c] = 0.f;

    for (int kc = 0; kc < NC1; ++kc) {
        cp_wait0();
        __syncthreads();
        if (kc < NC1 - 1) { copyB1(kc + 1); CP_COMMIT; }

        uint32_t bBuf = (kc & 1) * 16384;
        uint4 va[2][2];
#pragma unroll
        for (int mi = 0; mi < 2; mi++) {
            va[mi][0] = lds128(aBase + (mi * 16) * (SA_E * 4) + kc * 64);
            va[mi][1] = lds128(aBase + (mi * 16 + 8) * (SA_E * 4) + kc * 64);
        }
#pragma unroll
        for (int j = 0; j < 8; j++) {
            uint4 vb = lds128(b1Base + bBuf + j * 512);
#pragma unroll
            for (int mi = 0; mi < 2; mi++) {
                mma_tf32(acc[mi][j], va[mi][0].x, va[mi][1].x, va[mi][0].y, va[mi][1].y,
                         vb.x, vb.y);
                mma_tf32(acc[mi][j], va[mi][0].z, va[mi][1].z, va[mi][0].w, va[mi][1].w,
                         vb.z, vb.w);
            }
        }
    }
    __syncthreads();          // A reads done; B1 dead

    copyB2(0); CP_COMMIT;     // overlaps epilogue 1

    // ---- Epilogue 1: +gu[batch], ReLU, tf32-cvt -> H smem (k-permuted) ----
    {
        float* H = (float*)(smem + H_OFF);
#pragma unroll
        for (int mi = 0; mi < 2; mi++) {
            int r0 = rA + mi * 16 + lq;
            int r1 = r0 + 8;
            int g0 = batch[min(m0 + r0, N_NODES - 1)];
            int g1 = batch[min(m0 + r1, N_NODES - 1)];
            g0 = min(max(g0, 0), NG - 1);
            g1 = min(max(g1, 0), NG - 1);
            const float* gu0 = g_gu + g0 * HID;
            const float* gu1 = g_gu + g1 * HID;
#pragma unroll
            for (int nf = 0; nf < 8; nf++) {
                int c = nw * 64 + nf * 8 + lr * 2;
                float2 u0 = *(const float2*)(gu0 + c);
                float2 u1 = *(const float2*)(gu1 + c);
                int p0 = kperm(c), p1 = kperm(c + 1);
                H[r0 * SH_E + p0] = __uint_as_float(f2tf(fmaxf(acc[mi][nf][0] + u0.x, 0.f)));
                H[r0 * SH_E + p1] = __uint_as_float(f2tf(fmaxf(acc[mi][nf][1] + u0.y, 0.f)));
                H[r1 * SH_E + p0] = __uint_as_float(f2tf(fmaxf(acc[mi][nf][2] + u1.x, 0.f)));
                H[r1 * SH_E + p1] = __uint_as_float(f2tf(fmaxf(acc[mi][nf][3] + u1.y, 0.f)));
            }
        }
    }

    // ---------------- Phase 2: warp tile 32x32, 16 chunks ----------------
    const uint32_t hBase = sbase + H_OFF + (rA + lq) * (SH_E * 4) + lr * 16;

    float acc2[2][4][4];
#pragma unroll
    for (int a = 0; a < 2; a++)
#pragma unroll
        for (int b = 0; b < 4; b++)
#pragma unroll
            for (int c = 0; c < 4; c++) acc2[a][b][c] = 0.f;

    for (int kc = 0; kc < 16; ++kc) {
        cp_wait0();
        __syncthreads();      // H visible (kc=0) + buffer reuse safety
        if (kc < 15) { copyB2(kc + 1); CP_COMMIT; }

        uint32_t bBuf = (kc & 1) * 8192;
        uint4 va[2][2];
#pragma unroll
        for (int mi = 0; mi < 2; mi++) {
            va[mi][0] = lds128(hBase + (mi * 16) * (SH_E * 4) + kc * 64);
            va[mi][1] = lds128(hBase + (mi * 16 + 8) * (SH_E * 4) + kc * 64);
        }
#pragma unroll
        for (int j = 0; j < 4; j++) {
            uint4 vb = lds128(b2Base + bBuf + j * 512);
#pragma unroll
            for (int mi = 0; mi < 2; mi++) {
                mma_tf32(acc2[mi][j], va[mi][0].x, va[mi][1].x, va[mi][0].y, va[mi][1].y,
                         vb.x, vb.y);
                mma_tf32(acc2[mi][j], va[mi][0].z, va[mi][1].z, va[mi][0].w, va[mi][1].w,
                         vb.z, vb.w);
            }
        }
    }

    // ---- Epilogue 2: + b2, store ----
    {
        int colB = nw * 32 + lr * 2;
#pragma unroll
        for (int mi = 0; mi < 2; mi++) {
            int r0 = rA + mi * 16 + lq;
            int gr0 = m0 + r0, gr1 = gr0 + 8;
#pragma unroll
            for (int nf = 0; nf < 4; nf++) {
                int col = colB + nf * 8;
                float2 bv = *(const float2*)(b2 + col);
                if (gr0 < N_NODES) {
                    float2 o = {acc2[mi][nf][0] + bv.x, acc2[mi][nf][1] + bv.y};
                    *(float2*)(out + (size_t)gr0 * ND + col) = o;
                }
                if (gr1 < N_NODES) {
                    float2 o = {acc2[mi][nf][2] + bv.x, acc2[mi][nf][3] + bv.y};
                    *(float2*)(out + (size_t)gr1 * ND + col) = o;
                }
            }
        }
    }
}

// ---------------- launch ----------------
extern "C" void kernel_launch(void* const* d_in, const int* in_sizes, int n_in,
                              void* d_out, int out_size) {
    const float* nodes   = (const float*)d_in[0];
    const float* edges   = (const float*)d_in[1];
    const int*   eindex  = (const int*)d_in[2];
    const int*   batch   = (const int*)d_in[3];
    const float* globals = (const float*)d_in[4];
    const float* W1      = (const float*)d_in[5];
    const float* b1      = (const float*)d_in[6];
    const float* W2      = (const float*)d_in[7];
    const float* b2      = (const float*)d_in[8];
    float*       out     = (float*)d_out;

    k_prep<<<5056, 256>>>(globals, W1, b1, W2);
    k_scatter<<<(N_EDGES * 12) / 256, 256>>>(edges, eindex + N_EDGES);

    cudaFuncSetAttribute(k_mlp_mma, cudaFuncAttributeMaxDynamicSharedMemorySize, SMEM_BYTES);
    k_mlp_mma<<<(N_NODES + 63) / 64, 256, SMEM_BYTES>>>(nodes, batch, b2, out);
}

// round 12
// speedup vs baseline: 2.5476x; 1.0060x over previous
#include <cuda_runtime.h>
#include <cuda_bf16.h>
#include <cstdint>

#define N_NODES 100000
#define N_EDGES 1600000
#define ND 128
#define ED 48
#define GD 64
#define NG 64
#define HID 256

// ---------------- device scratch ----------------
__device__ __align__(16) float g_agg[N_NODES * ED];
__device__ __align__(16) float g_gu[NG * HID];
// W1^T tf32 blob: [11 chunks][256 n][16 k] (k-permuted), fp32 storage
__device__ __align__(16) float g_w1t[11 * 256 * 16];
// W2^T tf32 blob: [16 chunks][128 n][16 k]
__device__ __align__(16) float g_w2t[16 * 128 * 16];

// ---------------- helpers ----------------
__device__ __forceinline__ uint32_t smem_u32(const void* p) {
    return (uint32_t)__cvta_generic_to_shared(p);
}
__device__ __forceinline__ void cp16(char* dst, const char* src) {
    uint32_t s = smem_u32(dst);
    asm volatile("cp.async.cg.shared.global [%0], [%1], 16;" :: "r"(s), "l"(src));
}
#define CP_COMMIT asm volatile("cp.async.commit_group;")
__device__ __forceinline__ void cp_wait0() { asm volatile("cp.async.wait_group 0;"); }
__device__ __forceinline__ void cp_wait1() { asm volatile("cp.async.wait_group 1;"); }

__device__ __forceinline__ uint32_t f2tf(float f) {
    uint32_t r;
    asm("cvt.rna.tf32.f32 %0, %1;" : "=r"(r) : "f"(f));
    return r;
}
__device__ __forceinline__ void mma_tf32(float d[4], uint32_t a0, uint32_t a1,
                                         uint32_t a2, uint32_t a3,
                                         uint32_t b0, uint32_t b1) {
    asm volatile("mma.sync.aligned.m16n8k8.row.col.f32.tf32.tf32.f32 "
                 "{%0,%1,%2,%3}, {%4,%5,%6,%7}, {%8,%9}, {%0,%1,%2,%3};"
                 : "+f"(d[0]), "+f"(d[1]), "+f"(d[2]), "+f"(d[3])
                 : "r"(a0), "r"(a1), "r"(a2), "r"(a3), "r"(b0), "r"(b1));
}
__device__ __forceinline__ uint4 lds128(uint32_t addr) {
    uint4 v;
    asm volatile("ld.shared.v4.b32 {%0,%1,%2,%3}, [%4];"
                 : "=r"(v.x), "=r"(v.y), "=r"(v.z), "=r"(v.w) : "r"(addr));
    return v;
}
__device__ __forceinline__ float4 ldg_cs128(const float* p) {
    float4 v;
    asm volatile("ld.global.cs.v4.f32 {%0,%1,%2,%3}, [%4];"
                 : "=f"(v.x), "=f"(v.y), "=f"(v.z), "=f"(v.w) : "l"(p));
    return v;
}

// k-permutation within a 16-chunk: logical k (4q+r) stored at 4r+q.
__device__ __forceinline__ int kperm(int c) {
    return (c & ~15) + 4 * (c & 3) + ((c >> 2) & 3);
}

// ---------------- Kernel: scatter-add (vector red, streaming reads) ----------------
__global__ void k_scatter(const float* __restrict__ edges,
                          const int* __restrict__ recv) {
    int idx = blockIdx.x * blockDim.x + threadIdx.x;
    if (idx >= N_EDGES * 12) return;
    int e = idx / 12;
    int c = idx - e * 12;
    float4 v = ldg_cs128(edges + (size_t)idx * 4);
    int r = recv[e];
    r = min(max(r, 0), N_NODES - 1);
    float* dst = g_agg + r * ED + c * 4;
    asm volatile("red.global.add.v4.f32 [%0], {%1,%2,%3,%4};"
                 :: "l"(dst), "f"(v.x), "f"(v.y), "f"(v.z), "f"(v.w) : "memory");
}

// ---------------- prep: zero agg | W1^T | W2^T ----------------
// grid = 4688 + 176 + 128 = 4992 blocks x 256 thr
__global__ void k_prep(const float* __restrict__ W1, const float* __restrict__ W2) {
    int b = blockIdx.x, t = threadIdx.x;
    if (b < 4688) {                       // zero g_agg
        int i = b * 256 + t;
        if (i < (N_NODES * ED) / 4)
            reinterpret_cast<float4*>(g_agg)[i] = make_float4(0.f, 0.f, 0.f, 0.f);
    } else if (b < 4864) {                // W1^T tf32 blob [11][256][16]
        int idx = (b - 4688) * 256 + t;   // 45056
        int p = idx & 15, n = (idx >> 4) & 255, chunk = idx >> 12;
        int kg = chunk * 16 + 4 * (p & 3) + (p >> 2);
        g_w1t[idx] = __uint_as_float(f2tf(W1[kg * HID + n]));
    } else {                              // W2^T tf32 blob [16][128][16]
        int idx = (b - 4864) * 256 + t;   // 32768
        int p = idx & 15, n = (idx >> 4) & 127, chunk = idx >> 11;
        int kg = chunk * 16 + 4 * (p & 3) + (p >> 2);
        g_w2t[idx] = __uint_as_float(f2tf(W2[kg * ND + n]));
    }
}

// ---------------- gu = globals @ W1c + b1 (fp32) ----------------
__global__ void k_gu(const float* __restrict__ gg, const float* __restrict__ W1,
                     const float* __restrict__ b1) {
    __shared__ float sg[GD];
    int g = blockIdx.x, j = threadIdx.x;
    if (j < GD) sg[j] = gg[g * GD + j];
    __syncthreads();
    float acc = b1[j];
#pragma unroll
    for (int k = 0; k < GD; k++)
        acc = fmaf(sg[k], W1[(ND + ED + k) * HID + j], acc);
    g_gu[g * HID + j] = acc;
}

// ---------------- fused MLP: tf32 mma, 64 rows/block, 2 CTAs/SM ----------------
// SMEM (bytes):
//  phase1: A  [0, 45056)  64 x 176 fp32 (704B stride, k-permuted)
//          B1 [46080, 95232)  ring-3 x 16384 (256n x 16k fp32)
//  phase2: H  [0, 69632)  64 x 272-stride fp32 (k-permuted, cols 0..255)
//          B2 [70656, 95232)  ring-3 x 8192 (128n x 16k fp32)
#define A_OFF  0
#define B1_OFF 46080
#define H_OFF  0
#define B2_OFF 70656
#define SMEM_BYTES 95232
#define SA_E 176
#define SH_E 272
#define NC1 11
#define NC2 16

__global__ void __launch_bounds__(256, 2) k_mlp_mma(
    const float* __restrict__ nodes, const int* __restrict__ batch,
    const float* __restrict__ b2, float* __restrict__ out) {
    extern __shared__ char smem[];
    const uint32_t sbase = smem_u32(smem);
    const int t = threadIdx.x;
    const int wid = t >> 5, lane = t & 31;
    const int m0 = blockIdx.x * 64;
    const int mw = wid >> 2;          // 0..1 -> 32-row band
    const int nw = wid & 3;           // 0..3
    const int rA = mw * 32;
    const int lq = lane >> 2;         // 0..7
    const int lr = lane & 3;          // 0..3

    auto copyB1 = [&](int kc) {
        char* dst = smem + B1_OFF + (kc % 3) * 16384;
        const char* src = (const char*)g_w1t + kc * 16384;
#pragma unroll
        for (int i = 0; i < 4; i++) {
            int u = (t + i * 256) * 16;
            cp16(dst + u, src + u);
        }
    };
    auto copyB2 = [&](int kc) {
        char* dst = smem + B2_OFF + (kc % 3) * 8192;
        const char* src = (const char*)g_w2t + kc * 8192;
#pragma unroll
        for (int i = 0; i < 2; i++) {
            int u = (t + i * 256) * 16;
            cp16(dst + u, src + u);
        }
    };

    copyB1(0); CP_COMMIT;
    copyB1(1); CP_COMMIT;

    // ---- stage X = [nodes | agg] -> A smem (tf32 bits, k-permuted) ----
    {
        float* A = (float*)(smem + A_OFF);
#pragma unroll
        for (int i = 0; i < 8; i++) {             // nodes: 64 rows x 32 quads
            int f4 = t + i * 256;
            int row = f4 >> 5, qq = f4 & 31;
            int gr = m0 + row;
            float4 v = make_float4(0.f, 0.f, 0.f, 0.f);
            if (gr < N_NODES) v = reinterpret_cast<const float4*>(nodes + (size_t)gr * ND)[qq];
            int base = row * SA_E + (qq >> 2) * 16 + (qq & 3);
            A[base]      = __uint_as_float(f2tf(v.x));
            A[base + 4]  = __uint_as_float(f2tf(v.y));
            A[base + 8]  = __uint_as_float(f2tf(v.z));
            A[base + 12] = __uint_as_float(f2tf(v.w));
        }
#pragma unroll
        for (int i = 0; i < 3; i++) {             // agg: 64 rows x 12 quads (k 128..175)
            int f4 = t + i * 256;
            if (f4 < 768) {
                int row = f4 / 12, j = f4 - row * 12;
                int gr = m0 + row;
                float4 v = make_float4(0.f, 0.f, 0.f, 0.f);
                if (gr < N_NODES) v = reinterpret_cast<const float4*>(g_agg + (size_t)gr * ED)[j];
                int qq = 32 + j;
                int base = row * SA_E + (qq >> 2) * 16 + (qq & 3);
                A[base]      = __uint_as_float(f2tf(v.x));
                A[base + 4]  = __uint_as_float(f2tf(v.y));
                A[base + 8]  = __uint_as_float(f2tf(v.z));
                A[base + 12] = __uint_as_float(f2tf(v.w));
            }
        }
    }

    // per-lane fragment addresses (bytes)
    const uint32_t aBase = sbase + A_OFF + (rA + lq) * (SA_E * 4) + lr * 16;
    const uint32_t b1Base = sbase + B1_OFF + (nw * 64 + lq) * 64 + lr * 16;
    const uint32_t b2Base = sbase + B2_OFF + (nw * 32 + lq) * 64 + lr * 16;

    // ---------------- Phase 1: warp tile 32x64, 11 chunks, ring-3 ----------------
    float acc[2][8][4];
#pragma unroll
    for (int a = 0; a < 2; a++)
#pragma unroll
        for (int b = 0; b < 8; b++)
#pragma unroll
            for (int c = 0; c < 4; c++) acc[a][b][c] = 0.f;

    for (int kc = 0; kc < NC1; ++kc) {
        if (kc < NC1 - 1) cp_wait1(); else cp_wait0();
        __syncthreads();
        if (kc + 2 < NC1) { copyB1(kc + 2); CP_COMMIT; }

        uint32_t bBuf = (kc % 3) * 16384;
        uint4 va[2][2];
#pragma unroll
        for (int mi = 0; mi < 2; mi++) {
            va[mi][0] = lds128(aBase + (mi * 16) * (SA_E * 4) + kc * 64);
            va[mi][1] = lds128(aBase + (mi * 16 + 8) * (SA_E * 4) + kc * 64);
        }
#pragma unroll
        for (int j = 0; j < 8; j++) {
            uint4 vb = lds128(b1Base + bBuf + j * 512);
#pragma unroll
            for (int mi = 0; mi < 2; mi++) {
                mma_tf32(acc[mi][j], va[mi][0].x, va[mi][1].x, va[mi][0].y, va[mi][1].y,
                         vb.x, vb.y);
                mma_tf32(acc[mi][j], va[mi][0].z, va[mi][1].z, va[mi][0].w, va[mi][1].w,
                         vb.z, vb.w);
            }
        }
    }
    __syncthreads();          // A/B1 reads done; regions reusable

    copyB2(0); CP_COMMIT;     // overlap epilogue 1
    copyB2(1); CP_COMMIT;

    // ---- Epilogue 1: +gu[batch], ReLU, tf32-cvt -> H smem (k-permuted) ----
    {
        float* H = (float*)(smem + H_OFF);
#pragma unroll
        for (int mi = 0; mi < 2; mi++) {
            int r0 = rA + mi * 16 + lq;
            int r1 = r0 + 8;
            int g0 = batch[min(m0 + r0, N_NODES - 1)];
            int g1 = batch[min(m0 + r1, N_NODES - 1)];
            g0 = min(max(g0, 0), NG - 1);
            g1 = min(max(g1, 0), NG - 1);
            const float* gu0 = g_gu + g0 * HID;
            const float* gu1 = g_gu + g1 * HID;
#pragma unroll
            for (int nf = 0; nf < 8; nf++) {
                int c = nw * 64 + nf * 8 + lr * 2;
                float2 u0 = *(const float2*)(gu0 + c);
                float2 u1 = *(const float2*)(gu1 + c);
                int p0 = kperm(c), p1 = kperm(c + 1);
                H[r0 * SH_E + p0] = __uint_as_float(f2tf(fmaxf(acc[mi][nf][0] + u0.x, 0.f)));
                H[r0 * SH_E + p1] = __uint_as_float(f2tf(fmaxf(acc[mi][nf][1] + u0.y, 0.f)));
                H[r1 * SH_E + p0] = __uint_as_float(f2tf(fmaxf(acc[mi][nf][2] + u1.x, 0.f)));
                H[r1 * SH_E + p1] = __uint_as_float(f2tf(fmaxf(acc[mi][nf][3] + u1.y, 0.f)));
            }
        }
    }

    // ---------------- Phase 2: warp tile 32x32, 16 chunks, ring-3 ----------------
    const uint32_t hBase = sbase + H_OFF + (rA + lq) * (SH_E * 4) + lr * 16;

    float acc2[2][4][4];
#pragma unroll
    for (int a = 0; a < 2; a++)
#pragma unroll
        for (int b = 0; b < 4; b++)
#pragma unroll
            for (int c = 0; c < 4; c++) acc2[a][b][c] = 0.f;

    for (int kc = 0; kc < NC2; ++kc) {
        if (kc < NC2 - 1) cp_wait1(); else cp_wait0();
        __syncthreads();      // also publishes H at kc=0
        if (kc + 2 < NC2) { copyB2(kc + 2); CP_COMMIT; }

        uint32_t bBuf = (kc % 3) * 8192;
        uint4 va[2][2];
#pragma unroll
        for (int mi = 0; mi < 2; mi++) {
            va[mi][0] = lds128(hBase + (mi * 16) * (SH_E * 4) + kc * 64);
            va[mi][1] = lds128(hBase + (mi * 16 + 8) * (SH_E * 4) + kc * 64);
        }
#pragma unroll
        for (int j = 0; j < 4; j++) {
            uint4 vb = lds128(b2Base + bBuf + j * 512);
#pragma unroll
            for (int mi = 0; mi < 2; mi++) {
                mma_tf32(acc2[mi][j], va[mi][0].x, va[mi][1].x, va[mi][0].y, va[mi][1].y,
                         vb.x, vb.y);
                mma_tf32(acc2[mi][j], va[mi][0].z, va[mi][1].z, va[mi][0].w, va[mi][1].w,
                         vb.z, vb.w);
            }
        }
    }

    // ---- Epilogue 2: + b2, store ----
    {
        int colB = nw * 32 + lr * 2;
#pragma unroll
        for (int mi = 0; mi < 2; mi++) {
            int r0 = rA + mi * 16 + lq;
            int gr0 = m0 + r0, gr1 = gr0 + 8;
#pragma unroll
            for (int nf = 0; nf < 4; nf++) {
                int col = colB + nf * 8;
                float2 bv = *(const float2*)(b2 + col);
                if (gr0 < N_NODES) {
                    float2 o = {acc2[mi][nf][0] + bv.x, acc2[mi][nf][1] + bv.y};
                    *(float2*)(out + (size_t)gr0 * ND + col) = o;
                }
                if (gr1 < N_NODES) {
                    float2 o = {acc2[mi][nf][2] + bv.x, acc2[mi][nf][3] + bv.y};
                    *(float2*)(out + (size_t)gr1 * ND + col) = o;
                }
            }
        }
    }
}

// ---------------- launch ----------------
extern "C" void kernel_launch(void* const* d_in, const int* in_sizes, int n_in,
                              void* d_out, int out_size) {
    const float* nodes   = (const float*)d_in[0];
    const float* edges   = (const float*)d_in[1];
    const int*   eindex  = (const int*)d_in[2];
    const int*   batch   = (const int*)d_in[3];
    const float* globals = (const float*)d_in[4];
    const float* W1      = (const float*)d_in[5];
    const float* b1      = (const float*)d_in[6];
    const float* W2      = (const float*)d_in[7];
    const float* b2      = (const float*)d_in[8];
    float*       out     = (float*)d_out;

    // launch order chosen so k_mlp_mma is the 4th launch (ncu capture slot)
    k_prep<<<4992, 256>>>(W1, W2);
    k_scatter<<<(N_EDGES * 12) / 256, 256>>>(edges, eindex + N_EDGES);
    k_gu<<<NG, HID>>>(globals, W1, b1);

    cudaFuncSetAttribute(k_mlp_mma, cudaFuncAttributeMaxDynamicSharedMemorySize, SMEM_BYTES);
    k_mlp_mma<<<(N_NODES + 63) / 64, 256, SMEM_BYTES>>>(nodes, batch, b2, out);
}

// round 13
// speedup vs baseline: 2.6194x; 1.0282x over previous
#include <cuda_runtime.h>
#include <cuda_bf16.h>
#include <cstdint>

#define N_NODES 100000
#define N_EDGES 1600000
#define ND 128
#define ED 48
#define GD 64
#define NG 64
#define HID 256

// ---------------- device scratch ----------------
__device__ __align__(16) float g_agg[N_NODES * ED];
__device__ __align__(16) float g_gu[NG * HID];
// W1^T tf32 blob: [11 chunks][256 n][16 k] (k-permuted), fp32 storage
__device__ __align__(16) float g_w1t[11 * 256 * 16];
// W2^T tf32 blob: [16 chunks][128 n][16 k]
__device__ __align__(16) float g_w2t[16 * 128 * 16];

// ---------------- helpers ----------------
__device__ __forceinline__ uint32_t smem_u32(const void* p) {
    return (uint32_t)__cvta_generic_to_shared(p);
}
__device__ __forceinline__ void cp16(char* dst, const char* src) {
    uint32_t s = smem_u32(dst);
    asm volatile("cp.async.cg.shared.global [%0], [%1], 16;" :: "r"(s), "l"(src));
}
#define CP_COMMIT asm volatile("cp.async.commit_group;")
__device__ __forceinline__ void cp_wait0() { asm volatile("cp.async.wait_group 0;"); }

__device__ __forceinline__ uint32_t f2tf(float f) {
    uint32_t r;
    asm("cvt.rna.tf32.f32 %0, %1;" : "=r"(r) : "f"(f));
    return r;
}
__device__ __forceinline__ void mma_tf32(float d[4], uint32_t a0, uint32_t a1,
                                         uint32_t a2, uint32_t a3,
                                         uint32_t b0, uint32_t b1) {
    asm volatile("mma.sync.aligned.m16n8k8.row.col.f32.tf32.tf32.f32 "
                 "{%0,%1,%2,%3}, {%4,%5,%6,%7}, {%8,%9}, {%0,%1,%2,%3};"
                 : "+f"(d[0]), "+f"(d[1]), "+f"(d[2]), "+f"(d[3])
                 : "r"(a0), "r"(a1), "r"(a2), "r"(a3), "r"(b0), "r"(b1));
}
__device__ __forceinline__ uint4 lds128(uint32_t addr) {
    uint4 v;
    asm volatile("ld.shared.v4.b32 {%0,%1,%2,%3}, [%4];"
                 : "=r"(v.x), "=r"(v.y), "=r"(v.z), "=r"(v.w) : "r"(addr));
    return v;
}
__device__ __forceinline__ float4 ldg_cs128(const float* p) {
    float4 v;
    asm volatile("ld.global.cs.v4.f32 {%0,%1,%2,%3}, [%4];"
                 : "=f"(v.x), "=f"(v.y), "=f"(v.z), "=f"(v.w) : "l"(p));
    return v;
}

// k-permutation within a 16-chunk: logical k (4q+r) stored at 4r+q.
__device__ __forceinline__ int kperm(int c) {
    return (c & ~15) + 4 * (c & 3) + ((c >> 2) & 3);
}

// ---------------- Kernel: scatter-add (vector red, streaming reads) ----------------
__global__ void k_scatter(const float* __restrict__ edges,
                          const int* __restrict__ recv) {
    int idx = blockIdx.x * blockDim.x + threadIdx.x;
    if (idx >= N_EDGES * 12) return;
    int e = idx / 12;
    int c = idx - e * 12;
    float4 v = ldg_cs128(edges + (size_t)idx * 4);
    int r = recv[e];
    r = min(max(r, 0), N_NODES - 1);
    float* dst = g_agg + r * ED + c * 4;
    asm volatile("red.global.add.v4.f32 [%0], {%1,%2,%3,%4};"
                 :: "l"(dst), "f"(v.x), "f"(v.y), "f"(v.z), "f"(v.w) : "memory");
}

// ---------------- prep: zero agg | W1^T | W2^T ----------------
__global__ void k_prep(const float* __restrict__ W1, const float* __restrict__ W2) {
    int b = blockIdx.x, t = threadIdx.x;
    if (b < 4688) {                       // zero g_agg
        int i = b * 256 + t;
        if (i < (N_NODES * ED) / 4)
            reinterpret_cast<float4*>(g_agg)[i] = make_float4(0.f, 0.f, 0.f, 0.f);
    } else if (b < 4864) {                // W1^T tf32 blob [11][256][16]
        int idx = (b - 4688) * 256 + t;   // 45056
        int p = idx & 15, n = (idx >> 4) & 255, chunk = idx >> 12;
        int kg = chunk * 16 + 4 * (p & 3) + (p >> 2);
        g_w1t[idx] = __uint_as_float(f2tf(W1[kg * HID + n]));
    } else {                              // W2^T tf32 blob [16][128][16]
        int idx = (b - 4864) * 256 + t;   // 32768
        int p = idx & 15, n = (idx >> 4) & 127, chunk = idx >> 11;
        int kg = chunk * 16 + 4 * (p & 3) + (p >> 2);
        g_w2t[idx] = __uint_as_float(f2tf(W2[kg * ND + n]));
    }
}

// ---------------- gu = globals @ W1c + b1 (fp32) ----------------
__global__ void k_gu(const float* __restrict__ gg, const float* __restrict__ W1,
                     const float* __restrict__ b1) {
    __shared__ float sg[GD];
    int g = blockIdx.x, j = threadIdx.x;
    if (j < GD) sg[j] = gg[g * GD + j];
    __syncthreads();
    float acc = b1[j];
#pragma unroll
    for (int k = 0; k < GD; k++)
        acc = fmaf(sg[k], W1[(ND + ED + k) * HID + j], acc);
    g_gu[g * HID + j] = acc;
}

// ---------------- fused MLP: tf32 mma, 64 rows/block, 2 CTAs/SM ----------------
// SMEM (bytes):
//  phase1: A  [0, 45056)  64 x 176 fp32 (704B stride, k-permuted)
//          B1 [46080, 111616)  2 pair-bufs x 32768 (2 chunks of 256n x 16k)
//  phase2: H  [0, 69632)  64 x 272-stride fp32 (k-permuted, cols 0..255)
//          B2 [70656, 103424)  2 pair-bufs x 16384 (2 chunks of 128n x 16k)
#define A_OFF  0
#define B1_OFF 46080
#define H_OFF  0
#define B2_OFF 70656
#define SMEM_BYTES 111616
#define SA_E 176
#define SH_E 272
#define NC1 11
#define NP1 6
#define NP2 8

__global__ void __launch_bounds__(256, 2) k_mlp_mma(
    const float* __restrict__ nodes, const int* __restrict__ batch,
    const float* __restrict__ b2, float* __restrict__ out) {
    extern __shared__ char smem[];
    const uint32_t sbase = smem_u32(smem);
    const int t = threadIdx.x;
    const int wid = t >> 5, lane = t & 31;
    const int m0 = blockIdx.x * 64;
    const int mw = wid >> 2;          // 0..1 -> 32-row band
    const int nw = wid & 3;           // 0..3
    const int rA = mw * 32;
    const int lq = lane >> 2;         // 0..7
    const int lr = lane & 3;          // 0..3

    // copy ONE 16KB W1 chunk into pair-buffer slot
    auto copyB1 = [&](int kc) {
        char* dst = smem + B1_OFF + ((kc >> 1) & 1) * 32768 + (kc & 1) * 16384;
        const char* src = (const char*)g_w1t + kc * 16384;
#pragma unroll
        for (int i = 0; i < 4; i++) {
            int u = (t + i * 256) * 16;
            cp16(dst + u, src + u);
        }
    };
    // copy ONE 8KB W2 chunk
    auto copyB2 = [&](int kc) {
        char* dst = smem + B2_OFF + ((kc >> 1) & 1) * 16384 + (kc & 1) * 8192;
        const char* src = (const char*)g_w2t + kc * 8192;
#pragma unroll
        for (int i = 0; i < 2; i++) {
            int u = (t + i * 256) * 16;
            cp16(dst + u, src + u);
        }
    };

    copyB1(0); copyB1(1); CP_COMMIT;    // pair 0 in flight

    // ---- stage X = [nodes | agg] -> A smem (tf32 bits, k-permuted) ----
    {
        float* A = (float*)(smem + A_OFF);
#pragma unroll
        for (int i = 0; i < 8; i++) {             // nodes: 64 rows x 32 quads
            int f4 = t + i * 256;
            int row = f4 >> 5, qq = f4 & 31;
            int gr = m0 + row;
            float4 v = make_float4(0.f, 0.f, 0.f, 0.f);
            if (gr < N_NODES) v = reinterpret_cast<const float4*>(nodes + (size_t)gr * ND)[qq];
            int base = row * SA_E + (qq >> 2) * 16 + (qq & 3);
            A[base]      = __uint_as_float(f2tf(v.x));
            A[base + 4]  = __uint_as_float(f2tf(v.y));
            A[base + 8]  = __uint_as_float(f2tf(v.z));
            A[base + 12] = __uint_as_float(f2tf(v.w));
        }
#pragma unroll
        for (int i = 0; i < 3; i++) {             // agg: 64 rows x 12 quads (k 128..175)
            int f4 = t + i * 256;
            if (f4 < 768) {
                int row = f4 / 12, j = f4 - row * 12;
                int gr = m0 + row;
                float4 v = make_float4(0.f, 0.f, 0.f, 0.f);
                if (gr < N_NODES) v = reinterpret_cast<const float4*>(g_agg + (size_t)gr * ED)[j];
                int qq = 32 + j;
                int base = row * SA_E + (qq >> 2) * 16 + (qq & 3);
                A[base]      = __uint_as_float(f2tf(v.x));
                A[base + 4]  = __uint_as_float(f2tf(v.y));
                A[base + 8]  = __uint_as_float(f2tf(v.z));
                A[base + 12] = __uint_as_float(f2tf(v.w));
            }
        }
    }

    // per-lane fragment addresses (bytes)
    const uint32_t aBase = sbase + A_OFF + (rA + lq) * (SA_E * 4) + lr * 16;
    const uint32_t b1Base = sbase + B1_OFF + (nw * 64 + lq) * 64 + lr * 16;
    const uint32_t b2Base = sbase + B2_OFF + (nw * 32 + lq) * 64 + lr * 16;

    // ---------------- Phase 1: warp tile 32x64, 6 pair-iterations ----------------
    float acc[2][8][4];
#pragma unroll
    for (int a = 0; a < 2; a++)
#pragma unroll
        for (int b = 0; b < 8; b++)
#pragma unroll
            for (int c = 0; c < 4; c++) acc[a][b][c] = 0.f;

#pragma unroll
    for (int p = 0; p < NP1; ++p) {
        cp_wait0();
        __syncthreads();
        if (p < NP1 - 1) {
            copyB1(2 * p + 2);
            if (2 * p + 3 < NC1) copyB1(2 * p + 3);
            CP_COMMIT;
        }
#pragma unroll
        for (int ks = 0; ks < 2; ++ks) {
            int kc = 2 * p + ks;
            if (kc < NC1) {
                uint32_t bBuf = (uint32_t)(p & 1) * 32768 + (uint32_t)ks * 16384;
                uint4 va[2][2];
#pragma unroll
                for (int mi = 0; mi < 2; mi++) {
                    va[mi][0] = lds128(aBase + (mi * 16) * (SA_E * 4) + kc * 64);
                    va[mi][1] = lds128(aBase + (mi * 16 + 8) * (SA_E * 4) + kc * 64);
                }
#pragma unroll
                for (int j = 0; j < 8; j++) {
                    uint4 vb = lds128(b1Base + bBuf + j * 512);
#pragma unroll
                    for (int mi = 0; mi < 2; mi++) {
                        mma_tf32(acc[mi][j], va[mi][0].x, va[mi][1].x,
                                 va[mi][0].y, va[mi][1].y, vb.x, vb.y);
                        mma_tf32(acc[mi][j], va[mi][0].z, va[mi][1].z,
                                 va[mi][0].w, va[mi][1].w, vb.z, vb.w);
                    }
                }
            }
        }
    }
    __syncthreads();          // A/B1 reads done; regions reusable

    copyB2(0); copyB2(1); CP_COMMIT;   // pair 0; overlaps epilogue 1

    // ---- Epilogue 1: +gu[batch], ReLU, tf32-cvt -> H smem (k-permuted) ----
    {
        float* H = (float*)(smem + H_OFF);
#pragma unroll
        for (int mi = 0; mi < 2; mi++) {
            int r0 = rA + mi * 16 + lq;
            int r1 = r0 + 8;
            int g0 = batch[min(m0 + r0, N_NODES - 1)];
            int g1 = batch[min(m0 + r1, N_NODES - 1)];
            g0 = min(max(g0, 0), NG - 1);
            g1 = min(max(g1, 0), NG - 1);
            const float* gu0 = g_gu + g0 * HID;
            const float* gu1 = g_gu + g1 * HID;
#pragma unroll
            for (int nf = 0; nf < 8; nf++) {
                int c = nw * 64 + nf * 8 + lr * 2;
                float2 u0 = *(const float2*)(gu0 + c);
                float2 u1 = *(const float2*)(gu1 + c);
                int p0 = kperm(c), p1 = kperm(c + 1);
                H[r0 * SH_E + p0] = __uint_as_float(f2tf(fmaxf(acc[mi][nf][0] + u0.x, 0.f)));
                H[r0 * SH_E + p1] = __uint_as_float(f2tf(fmaxf(acc[mi][nf][1] + u0.y, 0.f)));
                H[r1 * SH_E + p0] = __uint_as_float(f2tf(fmaxf(acc[mi][nf][2] + u1.x, 0.f)));
                H[r1 * SH_E + p1] = __uint_as_float(f2tf(fmaxf(acc[mi][nf][3] + u1.y, 0.f)));
            }
        }
    }

    // ---------------- Phase 2: warp tile 32x32, 8 pair-iterations ----------------
    const uint32_t hBase = sbase + H_OFF + (rA + lq) * (SH_E * 4) + lr * 16;

    float acc2[2][4][4];
#pragma unroll
    for (int a = 0; a < 2; a++)
#pragma unroll
        for (int b = 0; b < 4; b++)
#pragma unroll
            for (int c = 0; c < 4; c++) acc2[a][b][c] = 0.f;

#pragma unroll
    for (int p = 0; p < NP2; ++p) {
        cp_wait0();
        __syncthreads();      // also publishes H at p=0
        if (p < NP2 - 1) { copyB2(2 * p + 2); copyB2(2 * p + 3); CP_COMMIT; }
#pragma unroll
        for (int ks = 0; ks < 2; ++ks) {
            int kc = 2 * p + ks;
            uint32_t bBuf = (uint32_t)(p & 1) * 16384 + (uint32_t)ks * 8192;
            uint4 va[2][2];
#pragma unroll
            for (int mi = 0; mi < 2; mi++) {
                va[mi][0] = lds128(hBase + (mi * 16) * (SH_E * 4) + kc * 64);
                va[mi][1] = lds128(hBase + (mi * 16 + 8) * (SH_E * 4) + kc * 64);
            }
#pragma unroll
            for (int j = 0; j < 4; j++) {
                uint4 vb = lds128(b2Base + bBuf + j * 512);
#pragma unroll
                for (int mi = 0; mi < 2; mi++) {
                    mma_tf32(acc2[mi][j], va[mi][0].x, va[mi][1].x,
                             va[mi][0].y, va[mi][1].y, vb.x, vb.y);
                    mma_tf32(acc2[mi][j], va[mi][0].z, va[mi][1].z,
                             va[mi][0].w, va[mi][1].w, vb.z, vb.w);
                }
            }
        }
    }

    // ---- Epilogue 2: + b2, store ----
    {
        int colB = nw * 32 + lr * 2;
#pragma unroll
        for (int mi = 0; mi < 2; mi++) {
            int r0 = rA + mi * 16 + lq;
            int gr0 = m0 + r0, gr1 = gr0 + 8;
#pragma unroll
            for (int nf = 0; nf < 4; nf++) {
                int col = colB + nf * 8;
                float2 bv = *(const float2*)(b2 + col);
                if (gr0 < N_NODES) {
                    float2 o = {acc2[mi][nf][0] + bv.x, acc2[mi][nf][1] + bv.y};
                    *(float2*)(out + (size_t)gr0 * ND + col) = o;
                }
                if (gr1 < N_NODES) {
                    float2 o = {acc2[mi][nf][2] + bv.x, acc2[mi][nf][3] + bv.y};
                    *(float2*)(out + (size_t)gr1 * ND + col) = o;
                }
            }
        }
    }
}

// ---------------- launch ----------------
extern "C" void kernel_launch(void* const* d_in, const int* in_sizes, int n_in,
                              void* d_out, int out_size) {
    const float* nodes   = (const float*)d_in[0];
    const float* edges   = (const float*)d_in[1];
    const int*   eindex  = (const int*)d_in[2];
    const int*   batch   = (const int*)d_in[3];
    const float* globals = (const float*)d_in[4];
    const float* W1      = (const float*)d_in[5];
    const float* b1      = (const float*)d_in[6];
    const float* W2      = (const float*)d_in[7];
    const float* b2      = (const float*)d_in[8];
    float*       out     = (float*)d_out;

    // launch order keeps k_mlp_mma as the 4th launch (ncu capture slot)
    k_prep<<<4992, 256>>>(W1, W2);
    k_scatter<<<(N_EDGES * 12) / 256, 256>>>(edges, eindex + N_EDGES);
    k_gu<<<NG, HID>>>(globals, W1, b1);

    cudaFuncSetAttribute(k_mlp_mma, cudaFuncAttributeMaxDynamicSharedMemorySize, SMEM_BYTES);
    k_mlp_mma<<<(N_NODES + 63) / 64, 256, SMEM_BYTES>>>(nodes, batch, b2, out);
}

// round 14
// speedup vs baseline: 2.7092x; 1.0343x over previous
#include <cuda_runtime.h>
#include <cuda_bf16.h>
#include <cstdint>

#define N_NODES 100000
#define N_EDGES 1600000
#define ND 128
#define ED 48
#define GD 64
#define NG 64
#define HID 256

// ---------------- device scratch ----------------
__device__ __align__(16) float g_agg[N_NODES * ED];
__device__ __align__(16) float g_gu[NG * HID];
// W1^T tf32 blob: [11 chunks][256 n][16 k] identity layout, fp32 storage
__device__ __align__(16) float g_w1t[11 * 256 * 16];
// W2^T tf32 blob: [16 chunks][128 n][16 k]
__device__ __align__(16) float g_w2t[16 * 128 * 16];

// ---------------- helpers ----------------
__device__ __forceinline__ uint32_t smem_u32(const void* p) {
    return (uint32_t)__cvta_generic_to_shared(p);
}
__device__ __forceinline__ void cp16(char* dst, const char* src) {
    uint32_t s = smem_u32(dst);
    asm volatile("cp.async.cg.shared.global [%0], [%1], 16;" :: "r"(s), "l"(src));
}
#define CP_COMMIT asm volatile("cp.async.commit_group;")
__device__ __forceinline__ void cp_wait0() { asm volatile("cp.async.wait_group 0;"); }

__device__ __forceinline__ uint32_t f2tf(float f) {
    uint32_t r;
    asm("cvt.rna.tf32.f32 %0, %1;" : "=r"(r) : "f"(f));
    return r;
}
__device__ __forceinline__ void mma_tf32(float d[4], uint32_t a0, uint32_t a1,
                                         uint32_t a2, uint32_t a3,
                                         uint32_t b0, uint32_t b1) {
    asm volatile("mma.sync.aligned.m16n8k8.row.col.f32.tf32.tf32.f32 "
                 "{%0,%1,%2,%3}, {%4,%5,%6,%7}, {%8,%9}, {%0,%1,%2,%3};"
                 : "+f"(d[0]), "+f"(d[1]), "+f"(d[2]), "+f"(d[3])
                 : "r"(a0), "r"(a1), "r"(a2), "r"(a3), "r"(b0), "r"(b1));
}
__device__ __forceinline__ uint4 lds128(uint32_t addr) {
    uint4 v;
    asm volatile("ld.shared.v4.b32 {%0,%1,%2,%3}, [%4];"
                 : "=r"(v.x), "=r"(v.y), "=r"(v.z), "=r"(v.w) : "r"(addr));
    return v;
}
__device__ __forceinline__ float4 ldg_cs128(const float* p) {
    float4 v;
    asm volatile("ld.global.cs.v4.f32 {%0,%1,%2,%3}, [%4];"
                 : "=f"(v.x), "=f"(v.y), "=f"(v.z), "=f"(v.w) : "l"(p));
    return v;
}
// convert float4 to tf32 bits, return as float4 bit-pattern
__device__ __forceinline__ float4 tf4(float4 v) {
    float4 r;
    r.x = __uint_as_float(f2tf(v.x));
    r.y = __uint_as_float(f2tf(v.y));
    r.z = __uint_as_float(f2tf(v.z));
    r.w = __uint_as_float(f2tf(v.w));
    return r;
}

// ---------------- Kernel: scatter-add (vector red, streaming reads) ----------------
__global__ void k_scatter(const float* __restrict__ edges,
                          const int* __restrict__ recv) {
    int idx = blockIdx.x * blockDim.x + threadIdx.x;
    if (idx >= N_EDGES * 12) return;
    int e = idx / 12;
    int c = idx - e * 12;
    float4 v = ldg_cs128(edges + (size_t)idx * 4);
    int r = recv[e];
    r = min(max(r, 0), N_NODES - 1);
    float* dst = g_agg + r * ED + c * 4;
    asm volatile("red.global.add.v4.f32 [%0], {%1,%2,%3,%4};"
                 :: "l"(dst), "f"(v.x), "f"(v.y), "f"(v.z), "f"(v.w) : "memory");
}

// ---------------- prep: zero agg | W1^T | W2^T (identity layouts) ----------------
__global__ void k_prep(const float* __restrict__ W1, const float* __restrict__ W2) {
    int b = blockIdx.x, t = threadIdx.x;
    if (b < 4688) {                       // zero g_agg
        int i = b * 256 + t;
        if (i < (N_NODES * ED) / 4)
            reinterpret_cast<float4*>(g_agg)[i] = make_float4(0.f, 0.f, 0.f, 0.f);
    } else if (b < 4864) {                // W1^T tf32 blob [11][256][16]
        int idx = (b - 4688) * 256 + t;   // 45056
        int p = idx & 15, n = (idx >> 4) & 255, chunk = idx >> 12;
        int kg = chunk * 16 + p;
        g_w1t[idx] = __uint_as_float(f2tf(W1[kg * HID + n]));
    } else {                              // W2^T tf32 blob [16][128][16]
        int idx = (b - 4864) * 256 + t;   // 32768
        int p = idx & 15, n = (idx >> 4) & 127, chunk = idx >> 11;
        int kg = chunk * 16 + p;
        g_w2t[idx] = __uint_as_float(f2tf(W2[kg * ND + n]));
    }
}

// ---------------- gu = globals @ W1c + b1 (fp32) ----------------
__global__ void k_gu(const float* __restrict__ gg, const float* __restrict__ W1,
                     const float* __restrict__ b1) {
    __shared__ float sg[GD];
    int g = blockIdx.x, j = threadIdx.x;
    if (j < GD) sg[j] = gg[g * GD + j];
    __syncthreads();
    float acc = b1[j];
#pragma unroll
    for (int k = 0; k < GD; k++)
        acc = fmaf(sg[k], W1[(ND + ED + k) * HID + j], acc);
    g_gu[g * HID + j] = acc;
}

// ---------------- fused MLP: tf32 mma, 64 rows/block, 2 CTAs/SM ----------------
// SMEM (bytes):
//  phase1: A  [0, 45056)  64 x 176 fp32 (identity layout)
//          B1 [46080, 111616)  2 pair-bufs x 32768 (2 chunks of 256n x 16k)
//  phase2: H  [0, 69632)  64 x 272-stride fp32 (identity, cols 0..255)
//          B2 [70656, 103424)  2 pair-bufs x 16384 (2 chunks of 128n x 16k)
#define A_OFF  0
#define B1_OFF 46080
#define H_OFF  0
#define B2_OFF 70656
#define SMEM_BYTES 111616
#define SA_E 176
#define SH_E 272
#define NC1 11
#define NP1 6
#define NP2 8

__global__ void __launch_bounds__(256, 2) k_mlp_mma(
    const float* __restrict__ nodes, const int* __restrict__ batch,
    const float* __restrict__ b2, float* __restrict__ out) {
    extern __shared__ char smem[];
    const uint32_t sbase = smem_u32(smem);
    const int t = threadIdx.x;
    const int wid = t >> 5, lane = t & 31;
    const int m0 = blockIdx.x * 64;
    const int mw = wid >> 2;          // 0..1 -> 32-row band
    const int nw = wid & 3;           // 0..3
    const int rA = mw * 32;
    const int lq = lane >> 2;         // 0..7
    const int lr = lane & 3;          // 0..3

    auto copyB1 = [&](int kc) {
        char* dst = smem + B1_OFF + ((kc >> 1) & 1) * 32768 + (kc & 1) * 16384;
        const char* src = (const char*)g_w1t + kc * 16384;
#pragma unroll
        for (int i = 0; i < 4; i++) {
            int u = (t + i * 256) * 16;
            cp16(dst + u, src + u);
        }
    };
    auto copyB2 = [&](int kc) {
        char* dst = smem + B2_OFF + ((kc >> 1) & 1) * 16384 + (kc & 1) * 8192;
        const char* src = (const char*)g_w2t + kc * 8192;
#pragma unroll
        for (int i = 0; i < 2; i++) {
            int u = (t + i * 256) * 16;
            cp16(dst + u, src + u);
        }
    };

    copyB1(0); copyB1(1); CP_COMMIT;    // pair 0 in flight

    // ---- stage X = [nodes | agg] -> A smem (tf32 bits, identity, STS.128) ----
    {
        float4* A4 = (float4*)(smem + A_OFF);   // note: SA_E=176 is /4 -> float4 stride 44
#pragma unroll
        for (int i = 0; i < 8; i++) {             // nodes: 64 rows x 32 quads
            int f4 = t + i * 256;
            int row = f4 >> 5, qq = f4 & 31;
            int gr = m0 + row;
            float4 v = make_float4(0.f, 0.f, 0.f, 0.f);
            if (gr < N_NODES) v = reinterpret_cast<const float4*>(nodes + (size_t)gr * ND)[qq];
            A4[row * 44 + qq] = tf4(v);
        }
#pragma unroll
        for (int i = 0; i < 3; i++) {             // agg: 64 rows x 12 quads (k 128..175)
            int f4 = t + i * 256;
            if (f4 < 768) {
                int row = f4 / 12, j = f4 - row * 12;
                int gr = m0 + row;
                float4 v = make_float4(0.f, 0.f, 0.f, 0.f);
                if (gr < N_NODES) v = reinterpret_cast<const float4*>(g_agg + (size_t)gr * ED)[j];
                A4[row * 44 + 32 + j] = tf4(v);
            }
        }
    }

    // per-lane fragment addresses (bytes)
    const uint32_t aBase = sbase + A_OFF + (rA + lq) * (SA_E * 4) + lr * 16;
    const uint32_t b1Base = sbase + B1_OFF + (nw * 64 + lq) * 64 + lr * 16;
    const uint32_t b2Base = sbase + B2_OFF + (nw * 32 + lq) * 64 + lr * 16;

    // ---------------- Phase 1: warp tile 32x64, 6 pair-iterations ----------------
    float acc[2][8][4];
#pragma unroll
    for (int a = 0; a < 2; a++)
#pragma unroll
        for (int b = 0; b < 8; b++)
#pragma unroll
            for (int c = 0; c < 4; c++) acc[a][b][c] = 0.f;

#pragma unroll
    for (int p = 0; p < NP1; ++p) {
        cp_wait0();
        __syncthreads();
        if (p < NP1 - 1) {
            copyB1(2 * p + 2);
            if (2 * p + 3 < NC1) copyB1(2 * p + 3);
            CP_COMMIT;
        }
        const int kc0 = 2 * p, kc1 = 2 * p + 1;
        const bool has1 = (kc1 < NC1);
        // load A fragments for BOTH chunks up front (deep LDS run)
        uint4 va0[2][2], va1[2][2];
#pragma unroll
        for (int mi = 0; mi < 2; mi++) {
            va0[mi][0] = lds128(aBase + (mi * 16) * (SA_E * 4) + kc0 * 64);
            va0[mi][1] = lds128(aBase + (mi * 16 + 8) * (SA_E * 4) + kc0 * 64);
        }
        if (has1) {
#pragma unroll
            for (int mi = 0; mi < 2; mi++) {
                va1[mi][0] = lds128(aBase + (mi * 16) * (SA_E * 4) + kc1 * 64);
                va1[mi][1] = lds128(aBase + (mi * 16 + 8) * (SA_E * 4) + kc1 * 64);
            }
        }
        uint32_t bBuf0 = (uint32_t)(p & 1) * 32768;
#pragma unroll
        for (int j = 0; j < 8; j++) {
            uint4 vb = lds128(b1Base + bBuf0 + j * 512);
#pragma unroll
            for (int mi = 0; mi < 2; mi++) {
                mma_tf32(acc[mi][j], va0[mi][0].x, va0[mi][1].x,
                         va0[mi][0].y, va0[mi][1].y, vb.x, vb.y);
                mma_tf32(acc[mi][j], va0[mi][0].z, va0[mi][1].z,
                         va0[mi][0].w, va0[mi][1].w, vb.z, vb.w);
            }
        }
        if (has1) {
            uint32_t bBuf1 = bBuf0 + 16384;
#pragma unroll
            for (int j = 0; j < 8; j++) {
                uint4 vb = lds128(b1Base + bBuf1 + j * 512);
#pragma unroll
                for (int mi = 0; mi < 2; mi++) {
                    mma_tf32(acc[mi][j], va1[mi][0].x, va1[mi][1].x,
                             va1[mi][0].y, va1[mi][1].y, vb.x, vb.y);
                    mma_tf32(acc[mi][j], va1[mi][0].z, va1[mi][1].z,
                             va1[mi][0].w, va1[mi][1].w, vb.z, vb.w);
                }
            }
        }
    }
    __syncthreads();          // A/B1 reads done; regions reusable

    copyB2(0); copyB2(1); CP_COMMIT;   // pair 0; overlaps epilogue 1

    // ---- Epilogue 1: +gu[batch], ReLU, tf32-cvt -> H smem (identity, float2) ----
    {
        float* H = (float*)(smem + H_OFF);
#pragma unroll
        for (int mi = 0; mi < 2; mi++) {
            int r0 = rA + mi * 16 + lq;
            int r1 = r0 + 8;
            int g0 = batch[min(m0 + r0, N_NODES - 1)];
            int g1 = batch[min(m0 + r1, N_NODES - 1)];
            g0 = min(max(g0, 0), NG - 1);
            g1 = min(max(g1, 0), NG - 1);
            const float* gu0 = g_gu + g0 * HID;
            const float* gu1 = g_gu + g1 * HID;
#pragma unroll
            for (int nf = 0; nf < 8; nf++) {
                int c = nw * 64 + nf * 8 + lr * 2;
                float2 u0 = *(const float2*)(gu0 + c);
                float2 u1 = *(const float2*)(gu1 + c);
                float2 h0, h1;
                h0.x = __uint_as_float(f2tf(fmaxf(acc[mi][nf][0] + u0.x, 0.f)));
                h0.y = __uint_as_float(f2tf(fmaxf(acc[mi][nf][1] + u0.y, 0.f)));
                h1.x = __uint_as_float(f2tf(fmaxf(acc[mi][nf][2] + u1.x, 0.f)));
                h1.y = __uint_as_float(f2tf(fmaxf(acc[mi][nf][3] + u1.y, 0.f)));
                *(float2*)(H + r0 * SH_E + c) = h0;
                *(float2*)(H + r1 * SH_E + c) = h1;
            }
        }
    }

    // ---------------- Phase 2: warp tile 32x32, 8 pair-iterations ----------------
    const uint32_t hBase = sbase + H_OFF + (rA + lq) * (SH_E * 4) + lr * 16;

    float acc2[2][4][4];
#pragma unroll
    for (int a = 0; a < 2; a++)
#pragma unroll
        for (int b = 0; b < 4; b++)
#pragma unroll
            for (int c = 0; c < 4; c++) acc2[a][b][c] = 0.f;

#pragma unroll
    for (int p = 0; p < NP2; ++p) {
        cp_wait0();
        __syncthreads();      // also publishes H at p=0
        if (p < NP2 - 1) { copyB2(2 * p + 2); copyB2(2 * p + 3); CP_COMMIT; }
        const int kc0 = 2 * p, kc1 = 2 * p + 1;
        uint4 va0[2][2], va1[2][2];
#pragma unroll
        for (int mi = 0; mi < 2; mi++) {
            va0[mi][0] = lds128(hBase + (mi * 16) * (SH_E * 4) + kc0 * 64);
            va0[mi][1] = lds128(hBase + (mi * 16 + 8) * (SH_E * 4) + kc0 * 64);
            va1[mi][0] = lds128(hBase + (mi * 16) * (SH_E * 4) + kc1 * 64);
            va1[mi][1] = lds128(hBase + (mi * 16 + 8) * (SH_E * 4) + kc1 * 64);
        }
        uint32_t bBuf0 = (uint32_t)(p & 1) * 16384;
#pragma unroll
        for (int j = 0; j < 4; j++) {
            uint4 vb = lds128(b2Base + bBuf0 + j * 512);
#pragma unroll
            for (int mi = 0; mi < 2; mi++) {
                mma_tf32(acc2[mi][j], va0[mi][0].x, va0[mi][1].x,
                         va0[mi][0].y, va0[mi][1].y, vb.x, vb.y);
                mma_tf32(acc2[mi][j], va0[mi][0].z, va0[mi][1].z,
                         va0[mi][0].w, va0[mi][1].w, vb.z, vb.w);
            }
        }
        uint32_t bBuf1 = bBuf0 + 8192;
#pragma unroll
        for (int j = 0; j < 4; j++) {
            uint4 vb = lds128(b2Base + bBuf1 + j * 512);
#pragma unroll
            for (int mi = 0; mi < 2; mi++) {
                mma_tf32(acc2[mi][j], va1[mi][0].x, va1[mi][1].x,
                         va1[mi][0].y, va1[mi][1].y, vb.x, vb.y);
                mma_tf32(acc2[mi][j], va1[mi][0].z, va1[mi][1].z,
                         va1[mi][0].w, va1[mi][1].w, vb.z, vb.w);
            }
        }
    }

    // ---- Epilogue 2: + b2, store ----
    {
        int colB = nw * 32 + lr * 2;
#pragma unroll
        for (int mi = 0; mi < 2; mi++) {
            int r0 = rA + mi * 16 + lq;
            int gr0 = m0 + r0, gr1 = gr0 + 8;
#pragma unroll
            for (int nf = 0; nf < 4; nf++) {
                int col = colB + nf * 8;
                float2 bv = *(const float2*)(b2 + col);
                if (gr0 < N_NODES) {
                    float2 o = {acc2[mi][nf][0] + bv.x, acc2[mi][nf][1] + bv.y};
                    *(float2*)(out + (size_t)gr0 * ND + col) = o;
                }
                if (gr1 < N_NODES) {
                    float2 o = {acc2[mi][nf][2] + bv.x, acc2[mi][nf][3] + bv.y};
                    *(float2*)(out + (size_t)gr1 * ND + col) = o;
                }
            }
        }
    }
}

// ---------------- launch ----------------
extern "C" void kernel_launch(void* const* d_in, const int* in_sizes, int n_in,
                              void* d_out, int out_size) {
    const float* nodes   = (const float*)d_in[0];
    const float* edges   = (const float*)d_in[1];
    const int*   eindex  = (const int*)d_in[2];
    const int*   batch   = (const int*)d_in[3];
    const float* globals = (const float*)d_in[4];
    const float* W1      = (const float*)d_in[5];
    const float* b1      = (const float*)d_in[6];
    const float* W2      = (const float*)d_in[7];
    const float* b2      = (const float*)d_in[8];
    float*       out     = (float*)d_out;

    // launch order keeps k_mlp_mma as the 4th launch (ncu capture slot)
    k_prep<<<4992, 256>>>(W1, W2);
    k_scatter<<<(N_EDGES * 12) / 256, 256>>>(edges, eindex + N_EDGES);
    k_gu<<<NG, HID>>>(globals, W1, b1);

    cudaFuncSetAttribute(k_mlp_mma, cudaFuncAttributeMaxDynamicSharedMemorySize, SMEM_BYTES);
    k_mlp_mma<<<(N_NODES + 63) / 64, 256, SMEM_BYTES>>>(nodes, batch, b2, out);
}